// round 1
// baseline (speedup 1.0000x reference)
#include <cuda_runtime.h>
#include <cuda_bf16.h>
#include <cstdint>

// Problem constants
#define BATCH 4
#define TSEQ  4096
#define CEMB  1024
#define HD    64
#define MTOT  (BATCH * TSEQ)          // 16384 tokens

__device__ float g_q[MTOT * HD];
__device__ float g_k[MTOT * HD];
__device__ float g_v[MTOT * HD];

// -------------------------------------------------------------------------
// QKV projection: dst[token][h] = sum_c x[token][c] * w[h][c]
// Tiled fp32 GEMM: M=16384, N=64, K=1024. BM=64, BN=64, BK=32, 256 threads,
// 4x4 microtile per thread. blockIdx.z selects q/k/v.
// -------------------------------------------------------------------------
#define GBM 64
#define GBK 32
#define GPAD 4   // row stride 36 floats: keeps float4 alignment, spreads banks

__global__ __launch_bounds__(256) void qkv_gemm(
    const float* __restrict__ x,
    const float* __restrict__ wq,
    const float* __restrict__ wk,
    const float* __restrict__ wv)
{
    __shared__ float As[GBM][GBK + GPAD];
    __shared__ float Bs[HD][GBK + GPAD];

    const float* w   = (blockIdx.z == 0) ? wq : (blockIdx.z == 1) ? wk : wv;
    float*       dst = (blockIdx.z == 0) ? g_q : (blockIdx.z == 1) ? g_k : g_v;

    const int m0  = blockIdx.x * GBM;
    const int tid = threadIdx.x;
    const int tx  = tid & 15;   // 0..15 -> output cols
    const int ty  = tid >> 4;   // 0..15 -> output rows

    float c[4][4] = {};

    for (int k0 = 0; k0 < CEMB; k0 += GBK) {
        // Load A (64x32) and B (64x32) tiles, float4 per thread x2
        #pragma unroll
        for (int it = 0; it < 2; it++) {
            int f  = tid + it * 256;       // 0..511
            int r  = f >> 3;               // 0..63
            int c4 = (f & 7) * 4;          // 0..28
            float4 va = *(const float4*)&x[(size_t)(m0 + r) * CEMB + k0 + c4];
            As[r][c4 + 0] = va.x; As[r][c4 + 1] = va.y;
            As[r][c4 + 2] = va.z; As[r][c4 + 3] = va.w;
            float4 vb = *(const float4*)&w[(size_t)r * CEMB + k0 + c4];
            Bs[r][c4 + 0] = vb.x; Bs[r][c4 + 1] = vb.y;
            Bs[r][c4 + 2] = vb.z; Bs[r][c4 + 3] = vb.w;
        }
        __syncthreads();

        #pragma unroll
        for (int kk = 0; kk < GBK; kk += 4) {
            float4 a[4], b[4];
            #pragma unroll
            for (int i = 0; i < 4; i++)
                a[i] = *(const float4*)&As[ty * 4 + i][kk];
            #pragma unroll
            for (int j = 0; j < 4; j++)
                b[j] = *(const float4*)&Bs[tx * 4 + j][kk];
            #pragma unroll
            for (int i = 0; i < 4; i++)
                #pragma unroll
                for (int j = 0; j < 4; j++) {
                    c[i][j] += a[i].x * b[j].x;
                    c[i][j] += a[i].y * b[j].y;
                    c[i][j] += a[i].z * b[j].z;
                    c[i][j] += a[i].w * b[j].w;
                }
        }
        __syncthreads();
    }

    #pragma unroll
    for (int i = 0; i < 4; i++)
        #pragma unroll
        for (int j = 0; j < 4; j++)
            dst[(size_t)(m0 + ty * 4 + i) * HD + tx * 4 + j] = c[i][j];
}

// -------------------------------------------------------------------------
// Flash attention with ALiBi + causal mask.
// 4 threads per query (16 dims each), 64 queries per block (256 threads).
// Key/value tiles of 64 staged in smem. Online softmax with lazy rescale.
// -------------------------------------------------------------------------
#define BQ 64
#define KN 64

__global__ __launch_bounds__(256) void attn_kernel(float* __restrict__ out)
{
    constexpr float SCALE = 0.03125f;               // 1024^-0.5
    constexpr float SLOPE = 0.70710678118654752f;   // 2^-0.5 (head 0 of 16)

    __shared__ float Ks[KN][HD];
    __shared__ float Vs[KN][HD];

    const int b   = blockIdx.y;
    // heavy blocks (large q0) first to reduce wave-tail imbalance
    const int q0  = (gridDim.x - 1 - blockIdx.x) * BQ;
    const int tid = threadIdx.x;
    const int qi  = tid >> 2;     // 0..63 query within block
    const int sub = tid & 3;      // 0..3  dim sub-slice
    const int i   = q0 + qi;      // global query index within batch

    // Load q slice (16 dims), pre-scaled
    float4 qv[4];
    {
        const size_t qoff = ((size_t)b * TSEQ + i) * HD + sub * 16;
        #pragma unroll
        for (int d4 = 0; d4 < 4; d4++) {
            float4 v = *(const float4*)&g_q[qoff + d4 * 4];
            v.x *= SCALE; v.y *= SCALE; v.z *= SCALE; v.w *= SCALE;
            qv[d4] = v;
        }
    }

    float acc[16] = {};
    float m = -1e30f;
    float l = 0.0f;

    const int nTiles = q0 / KN + 1;
    for (int tile = 0; tile < nTiles; tile++) {
        const int j0 = tile * KN;
        __syncthreads();
        // Stage K/V tiles (64x64 floats each), coalesced float4
        #pragma unroll
        for (int it = 0; it < 4; it++) {
            int f  = tid + it * 256;       // 0..1023
            int r  = f >> 4;               // 0..63
            int c4 = (f & 15) * 4;         // 0..60
            size_t g = ((size_t)b * TSEQ + j0 + r) * HD + c4;
            *(float4*)&Ks[r][c4] = *(const float4*)&g_k[g];
            *(float4*)&Vs[r][c4] = *(const float4*)&g_v[g];
        }
        __syncthreads();

        const bool diag = (tile == nTiles - 1);

        for (int j = 0; j < KN; j++) {
            // dot(q, k_j) over this thread's 16 dims
            const float4* kr = (const float4*)&Ks[j][sub * 16];
            float s = 0.0f;
            #pragma unroll
            for (int d4 = 0; d4 < 4; d4++) {
                float4 kv = kr[d4];
                s += qv[d4].x * kv.x;
                s += qv[d4].y * kv.y;
                s += qv[d4].z * kv.z;
                s += qv[d4].w * kv.w;
            }
            // full-warp converged reduction across the 4 sub-slices
            s += __shfl_xor_sync(0xffffffffu, s, 1);
            s += __shfl_xor_sync(0xffffffffu, s, 2);

            const float dist = (float)(j0 + j - i);
            s += SLOPE * dist;
            if (diag && dist > 0.0f) s = -1e30f;   // causal mask (uniform loop)

            float m_new = fmaxf(m, s);
            if (m_new > m) {
                float corr = __expf(m - m_new);
                l *= corr;
                #pragma unroll
                for (int d = 0; d < 16; d++) acc[d] *= corr;
                m = m_new;
            }
            float p = __expf(s - m);
            l += p;

            const float4* vr = (const float4*)&Vs[j][sub * 16];
            #pragma unroll
            for (int d4 = 0; d4 < 4; d4++) {
                float4 vv = vr[d4];
                acc[d4 * 4 + 0] += p * vv.x;
                acc[d4 * 4 + 1] += p * vv.y;
                acc[d4 * 4 + 2] += p * vv.z;
                acc[d4 * 4 + 3] += p * vv.w;
            }
        }
    }

    const float inv = 1.0f / l;
    const size_t ooff = ((size_t)b * TSEQ + i) * HD + sub * 16;
    #pragma unroll
    for (int d = 0; d < 16; d++)
        out[ooff + d] = acc[d] * inv;
}

// -------------------------------------------------------------------------
extern "C" void kernel_launch(void* const* d_in, const int* in_sizes, int n_in,
                              void* d_out, int out_size)
{
    const float* x  = (const float*)d_in[0];
    const float* wq = (const float*)d_in[1];
    const float* wk = (const float*)d_in[2];
    const float* wv = (const float*)d_in[3];
    float* out = (float*)d_out;

    (void)in_sizes; (void)n_in; (void)out_size;

    dim3 ggrid(MTOT / GBM, 1, 3);   // 256 x 1 x 3
    qkv_gemm<<<ggrid, 256>>>(x, wq, wk, wv);

    dim3 agrid(TSEQ / BQ, BATCH);   // 64 x 4
    attn_kernel<<<agrid, 256>>>(out);
}

// round 2
// speedup vs baseline: 2.6283x; 2.6283x over previous
#include <cuda_runtime.h>
#include <cuda_bf16.h>
#include <cstdint>

// Problem constants
#define BATCH 4
#define TSEQ  4096
#define CEMB  1024
#define HD    64
#define MTOT  (BATCH * TSEQ)          // 16384 tokens

__device__ float g_q[MTOT * HD];
__device__ float g_k[MTOT * HD];
__device__ float g_v[MTOT * HD];

// -------------------------------------------------------------------------
// QKV projection: dst[token][h] = sum_c x[token][c] * w[h][c]
// Tiled fp32 GEMM: M=16384, N=64, K=1024. BM=64, BN=64, BK=32, 256 threads,
// 4x4 microtile per thread. blockIdx.z selects q/k/v.
// -------------------------------------------------------------------------
#define GBM 64
#define GBK 32
#define GPAD 4

__global__ __launch_bounds__(256) void qkv_gemm(
    const float* __restrict__ x,
    const float* __restrict__ wq,
    const float* __restrict__ wk,
    const float* __restrict__ wv)
{
    __shared__ float As[GBM][GBK + GPAD];
    __shared__ float Bs[HD][GBK + GPAD];

    const float* w   = (blockIdx.z == 0) ? wq : (blockIdx.z == 1) ? wk : wv;
    float*       dst = (blockIdx.z == 0) ? g_q : (blockIdx.z == 1) ? g_k : g_v;

    const int m0  = blockIdx.x * GBM;
    const int tid = threadIdx.x;
    const int tx  = tid & 15;
    const int ty  = tid >> 4;

    float c[4][4] = {};

    for (int k0 = 0; k0 < CEMB; k0 += GBK) {
        #pragma unroll
        for (int it = 0; it < 2; it++) {
            int f  = tid + it * 256;
            int r  = f >> 3;
            int c4 = (f & 7) * 4;
            float4 va = *(const float4*)&x[(size_t)(m0 + r) * CEMB + k0 + c4];
            As[r][c4 + 0] = va.x; As[r][c4 + 1] = va.y;
            As[r][c4 + 2] = va.z; As[r][c4 + 3] = va.w;
            float4 vb = *(const float4*)&w[(size_t)r * CEMB + k0 + c4];
            Bs[r][c4 + 0] = vb.x; Bs[r][c4 + 1] = vb.y;
            Bs[r][c4 + 2] = vb.z; Bs[r][c4 + 3] = vb.w;
        }
        __syncthreads();

        #pragma unroll
        for (int kk = 0; kk < GBK; kk += 4) {
            float4 a[4], b[4];
            #pragma unroll
            for (int i = 0; i < 4; i++)
                a[i] = *(const float4*)&As[ty * 4 + i][kk];
            #pragma unroll
            for (int j = 0; j < 4; j++)
                b[j] = *(const float4*)&Bs[tx * 4 + j][kk];
            #pragma unroll
            for (int i = 0; i < 4; i++)
                #pragma unroll
                for (int j = 0; j < 4; j++) {
                    c[i][j] += a[i].x * b[j].x;
                    c[i][j] += a[i].y * b[j].y;
                    c[i][j] += a[i].z * b[j].z;
                    c[i][j] += a[i].w * b[j].w;
                }
        }
        __syncthreads();
    }

    #pragma unroll
    for (int i = 0; i < 4; i++)
        #pragma unroll
        for (int j = 0; j < 4; j++)
            dst[(size_t)(m0 + ty * 4 + i) * HD + tx * 4 + j] = c[i][j];
}

// -------------------------------------------------------------------------
// Flash attention, GEMM-structured.
// Block = 256 threads (16x16), handles TWO query chunks of 64 (chunk c and
// 63-c) for perfect load balance: every block does exactly 65 KV tiles.
// Per tile: S = Q*K^T (register 4x4 microtile GEMM), amortized row softmax,
// P written over K buffer, then O += P*V (second register GEMM).
// -------------------------------------------------------------------------
#define BQ 64
#define KN 64
#define AP 68   // padded smem row stride (floats)
#define NCHUNK (TSEQ / BQ)   // 64

__global__ __launch_bounds__(256) void attn_kernel(float* __restrict__ out)
{
    constexpr float SCALE = 0.03125f;               // 1024^-0.5
    constexpr float SLOPE = 0.70710678118654752f;   // 2^-0.5 (head 0 of 16)

    extern __shared__ float sm[];
    float* Qs  = sm;                 // [BQ][AP]
    float* KPs = sm + BQ * AP;       // [KN][AP]  K tile, then P tile
    float* Vs  = sm + 2 * BQ * AP;   // [KN][AP]

    const int b   = blockIdx.y;
    const int tid = threadIdx.x;
    const int tx  = tid & 15;
    const int ty  = tid >> 4;

    #pragma unroll 1
    for (int half = 0; half < 2; half++) {
        const int chunk = half ? (NCHUNK - 1 - (int)blockIdx.x) : (int)blockIdx.x;
        const int q0 = chunk * BQ;

        __syncthreads();   // previous chunk finished with Qs
        // Load Q chunk, pre-scaled
        #pragma unroll
        for (int it = 0; it < 4; it++) {
            int f  = tid + it * 256;
            int r  = f >> 4;
            int c4 = (f & 15) * 4;
            float4 v = *(const float4*)&g_q[((size_t)b * TSEQ + q0 + r) * HD + c4];
            v.x *= SCALE; v.y *= SCALE; v.z *= SCALE; v.w *= SCALE;
            *(float4*)&Qs[r * AP + c4] = v;
        }

        float m[4], l[4], o[4][4];
        #pragma unroll
        for (int i = 0; i < 4; i++) {
            m[i] = -1e30f; l[i] = 0.0f;
            #pragma unroll
            for (int j = 0; j < 4; j++) o[i][j] = 0.0f;
        }

        const int nT = chunk + 1;
        #pragma unroll 1
        for (int t = 0; t < nT; t++) {
            const int j0 = t * KN;
            __syncthreads();   // previous tile's PV done
            #pragma unroll
            for (int it = 0; it < 4; it++) {
                int f  = tid + it * 256;
                int r  = f >> 4;
                int c4 = (f & 15) * 4;
                size_t g = ((size_t)b * TSEQ + j0 + r) * HD + c4;
                *(float4*)&KPs[r * AP + c4] = *(const float4*)&g_k[g];
                *(float4*)&Vs [r * AP + c4] = *(const float4*)&g_v[g];
            }
            __syncthreads();

            // ---- S = Q * K^T  (4x4 per thread) ----
            float s[4][4] = {};
            #pragma unroll
            for (int kk = 0; kk < HD; kk += 4) {
                float4 a[4], bb[4];
                #pragma unroll
                for (int i = 0; i < 4; i++)
                    a[i] = *(const float4*)&Qs[(ty * 4 + i) * AP + kk];
                #pragma unroll
                for (int j = 0; j < 4; j++)
                    bb[j] = *(const float4*)&KPs[(tx * 4 + j) * AP + kk];
                #pragma unroll
                for (int i = 0; i < 4; i++)
                    #pragma unroll
                    for (int j = 0; j < 4; j++) {
                        s[i][j] += a[i].x * bb[j].x;
                        s[i][j] += a[i].y * bb[j].y;
                        s[i][j] += a[i].z * bb[j].z;
                        s[i][j] += a[i].w * bb[j].w;
                    }
            }

            // ---- ALiBi + causal mask ----
            const bool diag = (t == nT - 1);
            #pragma unroll
            for (int i = 0; i < 4; i++) {
                const int qr = q0 + ty * 4 + i;
                #pragma unroll
                for (int j = 0; j < 4; j++) {
                    const int key = j0 + tx * 4 + j;
                    float sv = s[i][j] + SLOPE * (float)(key - qr);
                    if (diag && key > qr) sv = -1e30f;
                    s[i][j] = sv;
                }
            }

            // ---- online softmax (row stats amortized over 16 scores) ----
            #pragma unroll
            for (int i = 0; i < 4; i++) {
                float mx = fmaxf(fmaxf(s[i][0], s[i][1]), fmaxf(s[i][2], s[i][3]));
                #pragma unroll
                for (int off = 1; off < 16; off <<= 1)
                    mx = fmaxf(mx, __shfl_xor_sync(0xffffffffu, mx, off));
                const float mn   = fmaxf(m[i], mx);
                const float corr = __expf(m[i] - mn);
                m[i] = mn;
                l[i] *= corr;
                #pragma unroll
                for (int j = 0; j < 4; j++) o[i][j] *= corr;

                float rs = 0.0f;
                #pragma unroll
                for (int j = 0; j < 4; j++) {
                    float p = __expf(s[i][j] - mn);
                    s[i][j] = p;
                    rs += p;
                }
                #pragma unroll
                for (int off = 1; off < 16; off <<= 1)
                    rs += __shfl_xor_sync(0xffffffffu, rs, off);
                l[i] += rs;
            }

            __syncthreads();   // all threads done reading K
            // ---- write P over K buffer ----
            #pragma unroll
            for (int i = 0; i < 4; i++)
                *(float4*)&KPs[(ty * 4 + i) * AP + tx * 4] =
                    make_float4(s[i][0], s[i][1], s[i][2], s[i][3]);
            __syncthreads();

            // ---- O += P * V  (4x4 per thread) ----
            #pragma unroll
            for (int k = 0; k < KN; k += 4) {
                float4 a[4], bb[4];
                #pragma unroll
                for (int i = 0; i < 4; i++)
                    a[i] = *(const float4*)&KPs[(ty * 4 + i) * AP + k];
                #pragma unroll
                for (int u = 0; u < 4; u++)
                    bb[u] = *(const float4*)&Vs[(k + u) * AP + tx * 4];
                #pragma unroll
                for (int i = 0; i < 4; i++) {
                    o[i][0] += a[i].x * bb[0].x + a[i].y * bb[1].x
                             + a[i].z * bb[2].x + a[i].w * bb[3].x;
                    o[i][1] += a[i].x * bb[0].y + a[i].y * bb[1].y
                             + a[i].z * bb[2].y + a[i].w * bb[3].y;
                    o[i][2] += a[i].x * bb[0].z + a[i].y * bb[1].z
                             + a[i].z * bb[2].z + a[i].w * bb[3].z;
                    o[i][3] += a[i].x * bb[0].w + a[i].y * bb[1].w
                             + a[i].z * bb[2].w + a[i].w * bb[3].w;
                }
            }
        }

        // ---- normalize + store ----
        #pragma unroll
        for (int i = 0; i < 4; i++) {
            const float inv = 1.0f / l[i];
            float4 r = make_float4(o[i][0] * inv, o[i][1] * inv,
                                   o[i][2] * inv, o[i][3] * inv);
            *(float4*)&out[((size_t)b * TSEQ + q0 + ty * 4 + i) * HD + tx * 4] = r;
        }
    }
}

#define ATTN_SMEM (3 * BQ * AP * (int)sizeof(float))   // 52,224 B

// -------------------------------------------------------------------------
extern "C" void kernel_launch(void* const* d_in, const int* in_sizes, int n_in,
                              void* d_out, int out_size)
{
    const float* x  = (const float*)d_in[0];
    const float* wq = (const float*)d_in[1];
    const float* wk = (const float*)d_in[2];
    const float* wv = (const float*)d_in[3];
    float* out = (float*)d_out;

    (void)in_sizes; (void)n_in; (void)out_size;

    cudaFuncSetAttribute(attn_kernel,
                         cudaFuncAttributeMaxDynamicSharedMemorySize, ATTN_SMEM);

    dim3 ggrid(MTOT / GBM, 1, 3);
    qkv_gemm<<<ggrid, 256>>>(x, wq, wk, wv);

    dim3 agrid(NCHUNK / 2, BATCH);   // 32 x 4 = 128 blocks, 65 tiles each
    attn_kernel<<<agrid, 256, ATTN_SMEM>>>(out);
}

// round 3
// speedup vs baseline: 5.3288x; 2.0274x over previous
#include <cuda_runtime.h>
#include <cuda_bf16.h>
#include <cstdint>

// Problem constants
#define BATCH 4
#define TSEQ  4096
#define CEMB  1024
#define HD    64
#define MTOT  (BATCH * TSEQ)          // 16384 tokens

__device__ float g_q [MTOT * HD];     // [token][d] row-major
__device__ float g_kT[HD * MTOT];     // [d][token] column-major (transposed)
__device__ float g_v [MTOT * HD];     // [token][d] row-major
__device__ float g_wT[3 * CEMB * HD]; // [z][k][h] transposed weights

// -------------------------------------------------------------------------
// Weight transpose: wT[z][k][h] = w_z[h][k].  196K elements, trivial.
// -------------------------------------------------------------------------
__global__ void wtrans_kernel(const float* __restrict__ wq,
                              const float* __restrict__ wk,
                              const float* __restrict__ wv)
{
    const int idx = blockIdx.x * 256 + threadIdx.x;   // 0..65535
    const int z   = blockIdx.y;
    const float* w = (z == 0) ? wq : (z == 1) ? wk : wv;
    const int k = idx >> 6;
    const int h = idx & 63;
    g_wT[z * CEMB * HD + idx] = w[h * CEMB + k];
}

// -------------------------------------------------------------------------
// QKV projection: M=16384, N=64, K=1024.  BM=128, BK=32, 256 threads,
// 8x4 microtile.  Conflict-free: A-loads broadcast, B-loads row-consecutive.
// K output stored transposed ([d][token]); Q,V row-major.
// -------------------------------------------------------------------------
#define QBM 128
#define QBK 32
#define XST 36   // As row stride (floats)

__global__ __launch_bounds__(256) void qkv_gemm(const float* __restrict__ x)
{
    __shared__ float As[QBM * XST];   // x tile   [128 m][32 k]
    __shared__ float Ws[QBK * 64];    // wT tile  [32 k][64 h]

    const int z   = blockIdx.z;
    const float* wT = g_wT + z * CEMB * HD;

    const int m0  = blockIdx.x * QBM;
    const int tid = threadIdx.x;
    const int tx  = tid & 15;    // h/4
    const int ty  = tid >> 4;    // m/8
    const int tx4 = tx * 4;

    float c[8][4] = {};

    for (int k0 = 0; k0 < CEMB; k0 += QBK) {
        #pragma unroll
        for (int it = 0; it < 4; it++) {           // As: 128x32 floats
            int f  = tid + it * 256;
            int r  = f >> 3;
            int c4 = (f & 7) * 4;
            *(float4*)&As[r * XST + c4] =
                *(const float4*)&x[(size_t)(m0 + r) * CEMB + k0 + c4];
        }
        #pragma unroll
        for (int it = 0; it < 2; it++) {           // Ws: 32x64 floats
            int f  = tid + it * 256;
            int r  = f >> 4;
            int c4 = (f & 15) * 4;
            *(float4*)&Ws[r * 64 + c4] =
                *(const float4*)&wT[(size_t)(k0 + r) * HD + c4];
        }
        __syncthreads();

        #pragma unroll
        for (int kk = 0; kk < QBK; kk += 4) {
            float4 b0 = *(const float4*)&Ws[(kk + 0) * 64 + tx4];
            float4 b1 = *(const float4*)&Ws[(kk + 1) * 64 + tx4];
            float4 b2 = *(const float4*)&Ws[(kk + 2) * 64 + tx4];
            float4 b3 = *(const float4*)&Ws[(kk + 3) * 64 + tx4];
            #pragma unroll
            for (int i = 0; i < 8; i++) {
                float4 a = *(const float4*)&As[(ty * 8 + i) * XST + kk];
                c[i][0] += a.x * b0.x + a.y * b1.x + a.z * b2.x + a.w * b3.x;
                c[i][1] += a.x * b0.y + a.y * b1.y + a.z * b2.y + a.w * b3.y;
                c[i][2] += a.x * b0.z + a.y * b1.z + a.z * b2.z + a.w * b3.z;
                c[i][3] += a.x * b0.w + a.y * b1.w + a.z * b2.w + a.w * b3.w;
            }
        }
        __syncthreads();
    }

    if (z == 1) {
        // K: store transposed  g_kT[h][m]
        #pragma unroll
        for (int j = 0; j < 4; j++) {
            const size_t col = (size_t)(tx4 + j) * MTOT + m0 + ty * 8;
            *(float4*)&g_kT[col]     = make_float4(c[0][j], c[1][j], c[2][j], c[3][j]);
            *(float4*)&g_kT[col + 4] = make_float4(c[4][j], c[5][j], c[6][j], c[7][j]);
        }
    } else {
        float* dst = (z == 0) ? g_q : g_v;
        #pragma unroll
        for (int i = 0; i < 8; i++)
            *(float4*)&dst[(size_t)(m0 + ty * 8 + i) * HD + tx4] =
                make_float4(c[i][0], c[i][1], c[i][2], c[i][3]);
    }
}

// -------------------------------------------------------------------------
// Flash attention, conflict-free, fixed-reference softmax (scores bounded,
// ALiBi only subtracts -> no running max needed), double-buffered K/V.
// Block = 256 threads (16x16), 4x4 microtile, chunk c paired with 63-c.
// -------------------------------------------------------------------------
#define BQ 64
#define KN 64
#define QP 68          // Qs / Vs / Pb row stride
#define NCHUNK (TSEQ / BQ)   // 64

// smem float offsets
#define OFF_Q   0
#define OFF_P   (64 * QP)                 // 4352
#define OFF_K0  (2 * 64 * QP)             // 8704
#define OFF_K1  (OFF_K0 + 64 * 64)
#define OFF_V0  (OFF_K0 + 2 * 64 * 64)
#define OFF_V1  (OFF_V0 + 64 * QP)
#define ATTN_SMEM_FLOATS (OFF_V1 + 64 * QP)
#define ATTN_SMEM ((int)(ATTN_SMEM_FLOATS * sizeof(float)))   // 102,400 B

__global__ __launch_bounds__(256) void attn_kernel(float* __restrict__ out)
{
    constexpr float SCALE = 0.03125f;               // 1024^-0.5
    constexpr float SLOPE = 0.70710678118654752f;   // 2^-0.5 (head 0 of 16)

    extern __shared__ float sm[];
    float* Qs = sm + OFF_Q;
    float* Pb = sm + OFF_P;

    const int b   = blockIdx.y;
    const size_t bT = (size_t)b * TSEQ;
    const int tid = threadIdx.x;
    const int tx  = tid & 15;
    const int ty  = tid >> 4;
    const int tx4 = tx * 4;
    const int ty4 = ty * 4;

    const int rr  = tid >> 4;        // load row base (0..15)
    const int lc4 = (tid & 15) * 4;  // load col (0..60)

    #pragma unroll 1
    for (int half = 0; half < 2; half++) {
        const int chunk = half ? (NCHUNK - 1 - (int)blockIdx.x) : (int)blockIdx.x;
        const int q0 = chunk * BQ;
        const int nT = chunk + 1;

        __syncthreads();   // prior chunk fully done with smem
        // Load Q chunk (pre-scaled) + prologue K/V tile 0
        #pragma unroll
        for (int it = 0; it < 4; it++) {
            const int r = rr + it * 16;
            float4 v = *(const float4*)&g_q[(bT + q0 + r) * HD + lc4];
            v.x *= SCALE; v.y *= SCALE; v.z *= SCALE; v.w *= SCALE;
            *(float4*)&Qs[r * QP + lc4] = v;
            *(float4*)&sm[OFF_K0 + r * 64 + lc4] =
                *(const float4*)&g_kT[(size_t)r * MTOT + bT + lc4];
            *(float4*)&sm[OFF_V0 + r * QP + lc4] =
                *(const float4*)&g_v[(bT + r) * HD + lc4];
        }
        __syncthreads();

        float rs[4] = {};
        float o[4][4] = {};

        #pragma unroll 1
        for (int t = 0; t < nT; t++) {
            const float* Kt = sm + ((t & 1) ? OFF_K1 : OFF_K0);
            const float* Vs = sm + ((t & 1) ? OFF_V1 : OFF_V0);
            float* Kn = sm + ((t & 1) ? OFF_K0 : OFF_K1);
            float* Vn = sm + ((t & 1) ? OFF_V0 : OFF_V1);
            const int j0 = t * KN;

            // Prefetch next tile into registers (reload last tile harmlessly)
            const int j0n = (t + 1 < nT) ? j0 + KN : j0;
            float4 kreg[4], vreg[4];
            #pragma unroll
            for (int it = 0; it < 4; it++) {
                const int r = rr + it * 16;
                kreg[it] = *(const float4*)&g_kT[(size_t)r * MTOT + bT + j0n + lc4];
                vreg[it] = *(const float4*)&g_v[(bT + j0n + r) * HD + lc4];
            }

            // ---- S = Q * K^T  (outer-product accumulation) ----
            float s[4][4] = {};
            #pragma unroll
            for (int kk = 0; kk < HD; kk += 4) {
                float4 b0 = *(const float4*)&Kt[(kk + 0) * 64 + tx4];
                float4 b1 = *(const float4*)&Kt[(kk + 1) * 64 + tx4];
                float4 b2 = *(const float4*)&Kt[(kk + 2) * 64 + tx4];
                float4 b3 = *(const float4*)&Kt[(kk + 3) * 64 + tx4];
                #pragma unroll
                for (int i = 0; i < 4; i++) {
                    float4 a = *(const float4*)&Qs[(ty4 + i) * QP + kk];
                    s[i][0] += a.x * b0.x + a.y * b1.x + a.z * b2.x + a.w * b3.x;
                    s[i][1] += a.x * b0.y + a.y * b1.y + a.z * b2.y + a.w * b3.y;
                    s[i][2] += a.x * b0.z + a.y * b1.z + a.z * b2.z + a.w * b3.z;
                    s[i][3] += a.x * b0.w + a.y * b1.w + a.z * b2.w + a.w * b3.w;
                }
            }

            // ---- ALiBi + causal mask + exp (no running max: scores bounded) ----
            const bool diag = (t == nT - 1);
            #pragma unroll
            for (int i = 0; i < 4; i++) {
                const int qr = q0 + ty4 + i;
                #pragma unroll
                for (int j = 0; j < 4; j++) {
                    const int key = j0 + tx4 + j;
                    float p = __expf(s[i][j] + SLOPE * (float)(key - qr));
                    if (diag && key > qr) p = 0.0f;
                    s[i][j] = p;
                    rs[i] += p;
                }
            }

            // ---- stage P ----
            #pragma unroll
            for (int i = 0; i < 4; i++)
                *(float4*)&Pb[(ty4 + i) * QP + tx4] =
                    make_float4(s[i][0], s[i][1], s[i][2], s[i][3]);
            __syncthreads();   // P visible

            // ---- O += P * V ----
            #pragma unroll
            for (int k = 0; k < KN; k += 4) {
                float4 b0 = *(const float4*)&Vs[(k + 0) * QP + tx4];
                float4 b1 = *(const float4*)&Vs[(k + 1) * QP + tx4];
                float4 b2 = *(const float4*)&Vs[(k + 2) * QP + tx4];
                float4 b3 = *(const float4*)&Vs[(k + 3) * QP + tx4];
                #pragma unroll
                for (int i = 0; i < 4; i++) {
                    float4 a = *(const float4*)&Pb[(ty4 + i) * QP + k];
                    o[i][0] += a.x * b0.x + a.y * b1.x + a.z * b2.x + a.w * b3.x;
                    o[i][1] += a.x * b0.y + a.y * b1.y + a.z * b2.y + a.w * b3.y;
                    o[i][2] += a.x * b0.z + a.y * b1.z + a.z * b2.z + a.w * b3.z;
                    o[i][3] += a.x * b0.w + a.y * b1.w + a.z * b2.w + a.w * b3.w;
                }
            }

            // ---- stage next K/V tile ----
            #pragma unroll
            for (int it = 0; it < 4; it++) {
                const int r = rr + it * 16;
                *(float4*)&Kn[r * 64 + lc4] = kreg[it];
                *(float4*)&Vn[r * QP + lc4] = vreg[it];
            }
            __syncthreads();   // next tile visible; P/V free
        }

        // ---- row-sum reduce (once per chunk) + normalize + store ----
        #pragma unroll
        for (int i = 0; i < 4; i++) {
            float l = rs[i];
            #pragma unroll
            for (int off = 1; off < 16; off <<= 1)
                l += __shfl_xor_sync(0xffffffffu, l, off);
            const float inv = 1.0f / l;
            *(float4*)&out[(bT + q0 + ty4 + i) * HD + tx4] =
                make_float4(o[i][0] * inv, o[i][1] * inv,
                            o[i][2] * inv, o[i][3] * inv);
        }
    }
}

// -------------------------------------------------------------------------
extern "C" void kernel_launch(void* const* d_in, const int* in_sizes, int n_in,
                              void* d_out, int out_size)
{
    const float* x  = (const float*)d_in[0];
    const float* wq = (const float*)d_in[1];
    const float* wk = (const float*)d_in[2];
    const float* wv = (const float*)d_in[3];
    float* out = (float*)d_out;

    (void)in_sizes; (void)n_in; (void)out_size;

    cudaFuncSetAttribute(attn_kernel,
                         cudaFuncAttributeMaxDynamicSharedMemorySize, ATTN_SMEM);

    dim3 tgrid(CEMB * HD / 256, 3);
    wtrans_kernel<<<tgrid, 256>>>(wq, wk, wv);

    dim3 ggrid(MTOT / QBM, 1, 3);   // 128 x 1 x 3
    qkv_gemm<<<ggrid, 256>>>(x);

    dim3 agrid(NCHUNK / 2, BATCH);  // 32 x 4 = 128 blocks, 65 tiles each
    attn_kernel<<<agrid, 256, ATTN_SMEM>>>(out);
}

// round 5
// speedup vs baseline: 8.6228x; 1.6182x over previous
#include <cuda_runtime.h>
#include <cuda_bf16.h>
#include <cstdint>

// Problem constants
#define BATCH 4
#define TSEQ  4096
#define CEMB  1024
#define HD    64
#define MTOT  (BATCH * TSEQ)          // 16384 tokens

__device__ float g_q [MTOT * HD];     // [token][d] row-major
__device__ float g_kF[MTOT * HD];     // B-fragment-major per 64-key tile
__device__ float g_v [MTOT * HD];     // [token][d] row-major (tf32-rounded)
__device__ float g_wT[3 * CEMB * HD]; // [z][k][h] transposed weights

// ---- tf32 / mma helpers --------------------------------------------------
__device__ __forceinline__ uint32_t f2tf(float f) {
    uint32_t u;
    asm("cvt.rna.tf32.f32 %0, %1;" : "=r"(u) : "f"(f));
    return u;
}
__device__ __forceinline__ float tf32f(float f) { return __uint_as_float(f2tf(f)); }

__device__ __forceinline__ void mma8(float c[4], const uint32_t a[4],
                                     uint32_t b0, uint32_t b1) {
    asm volatile(
        "mma.sync.aligned.m16n8k8.row.col.f32.tf32.tf32.f32 "
        "{%0,%1,%2,%3}, {%4,%5,%6,%7}, {%8,%9}, {%0,%1,%2,%3};"
        : "+f"(c[0]), "+f"(c[1]), "+f"(c[2]), "+f"(c[3])
        : "r"(a[0]), "r"(a[1]), "r"(a[2]), "r"(a[3]), "r"(b0), "r"(b1));
}

#define CPA16(dst_s32, src) \
    asm volatile("cp.async.ca.shared.global [%0], [%1], 16;" :: "r"(dst_s32), "l"(src))
#define CPA_COMMIT() asm volatile("cp.async.commit_group;")
#define CPA_WAIT0()  asm volatile("cp.async.wait_group 0;" ::: "memory")

// -------------------------------------------------------------------------
// Weight transpose: wT[z][k][h] = w_z[h][k].
// -------------------------------------------------------------------------
__global__ void wtrans_kernel(const float* __restrict__ wq,
                              const float* __restrict__ wk,
                              const float* __restrict__ wv)
{
    const int idx = blockIdx.x * 256 + threadIdx.x;
    const int z   = blockIdx.y;
    const float* w = (z == 0) ? wq : (z == 1) ? wk : wv;
    const int k = idx >> 6;
    const int h = idx & 63;
    g_wT[z * CEMB * HD + idx] = w[h * CEMB + k];
}

// -------------------------------------------------------------------------
// QKV projection (fp32 FFMA). Q row-major; V row-major tf32-rounded;
// K stored B-fragment-major for the attention mma (tf32-rounded).
// -------------------------------------------------------------------------
#define QBM 128
#define QBK 32
#define XST 36

__global__ __launch_bounds__(256) void qkv_gemm(const float* __restrict__ x)
{
    __shared__ float As[QBM * XST];
    __shared__ float Ws[QBK * 64];

    const int z   = blockIdx.z;
    const float* wT = g_wT + z * CEMB * HD;

    const int m0  = blockIdx.x * QBM;
    const int tid = threadIdx.x;
    const int tx  = tid & 15;
    const int ty  = tid >> 4;
    const int tx4 = tx * 4;

    float c[8][4] = {};

    for (int k0 = 0; k0 < CEMB; k0 += QBK) {
        #pragma unroll
        for (int it = 0; it < 4; it++) {
            int f  = tid + it * 256;
            int r  = f >> 3;
            int c4 = (f & 7) * 4;
            *(float4*)&As[r * XST + c4] =
                *(const float4*)&x[(size_t)(m0 + r) * CEMB + k0 + c4];
        }
        #pragma unroll
        for (int it = 0; it < 2; it++) {
            int f  = tid + it * 256;
            int r  = f >> 4;
            int c4 = (f & 15) * 4;
            *(float4*)&Ws[r * 64 + c4] =
                *(const float4*)&wT[(size_t)(k0 + r) * HD + c4];
        }
        __syncthreads();

        #pragma unroll
        for (int kk = 0; kk < QBK; kk += 4) {
            float4 b0 = *(const float4*)&Ws[(kk + 0) * 64 + tx4];
            float4 b1 = *(const float4*)&Ws[(kk + 1) * 64 + tx4];
            float4 b2 = *(const float4*)&Ws[(kk + 2) * 64 + tx4];
            float4 b3 = *(const float4*)&Ws[(kk + 3) * 64 + tx4];
            #pragma unroll
            for (int i = 0; i < 8; i++) {
                float4 a = *(const float4*)&As[(ty * 8 + i) * XST + kk];
                c[i][0] += a.x * b0.x + a.y * b1.x + a.z * b2.x + a.w * b3.x;
                c[i][1] += a.x * b0.y + a.y * b1.y + a.z * b2.y + a.w * b3.y;
                c[i][2] += a.x * b0.z + a.y * b1.z + a.z * b2.z + a.w * b3.z;
                c[i][3] += a.x * b0.w + a.y * b1.w + a.z * b2.w + a.w * b3.w;
            }
        }
        __syncthreads();
    }

    if (z == 1) {
        // K: B-fragment-major. element (key, d): tile=key/64, d8=d/8,
        // n8=(key%64)/8, lane=(key%8)*4 + d%4, slot=(d%8)/4.
        // Here key=m0+ty*8+i, d=tx*4+j -> d8=tx/2, slot=tx&1, n8=ty&7,
        // lane=i*4+j, tile=(m0+ty*8)/64.
        const int tile = (m0 >> 6) + (ty >> 3);
        const int n8   = ty & 7;
        const int d8   = tx >> 1;
        const int slot = tx & 1;
        float* base = g_kF + (size_t)tile * 4096 + (d8 * 8 + n8) * 64 + slot;
        #pragma unroll
        for (int i = 0; i < 8; i++)
            #pragma unroll
            for (int j = 0; j < 4; j++)
                base[(i * 4 + j) * 2] = tf32f(c[i][j]);
    } else if (z == 2) {
        #pragma unroll
        for (int i = 0; i < 8; i++)
            *(float4*)&g_v[(size_t)(m0 + ty * 8 + i) * HD + tx4] =
                make_float4(tf32f(c[i][0]), tf32f(c[i][1]),
                            tf32f(c[i][2]), tf32f(c[i][3]));
    } else {
        #pragma unroll
        for (int i = 0; i < 8; i++)
            *(float4*)&g_q[(size_t)(m0 + ty * 8 + i) * HD + tx4] =
                make_float4(c[i][0], c[i][1], c[i][2], c[i][3]);
    }
}

// -------------------------------------------------------------------------
// Flash attention on tensor cores (mma.sync tf32).
// Block = 256 threads = 8 warps. Warp (mw,nw): mw=wid/2 rows 16, nw=wid&1
// cols 32. Q A-fragments register-resident per chunk. K fragment-major smem,
// V row-major pad-72 smem, P routed via smem pad-68. cp.async double buffer.
// -------------------------------------------------------------------------
#define NCHUNK (TSEQ / 64)
#define VP 72
#define PP 68
// smem float offsets
#define SK0 0
#define SK1 4096
#define SV0 8192
#define SV1 (SV0 + 64 * VP)
#define SPP (SV1 + 64 * VP)
#define SLS (SPP + 64 * PP)
#define ATTN_SMEM ((SLS + 128) * 4)   // 87,552 B

__global__ __launch_bounds__(256) void attn_kernel(float* __restrict__ out)
{
    constexpr float SCALE = 0.03125f;
    constexpr float SLOPE = 0.70710678118654752f;

    extern __shared__ float sm[];
    const int b    = blockIdx.y;
    const size_t bT = (size_t)b * TSEQ;
    const int tid  = threadIdx.x;
    const int lane = tid & 31;
    const int wid  = tid >> 5;
    const int mw   = wid >> 1;
    const int nw   = wid & 1;
    const int g    = lane >> 2;
    const int t    = lane & 3;

    #pragma unroll 1
    for (int half = 0; half < 2; half++) {
        const int chunk = half ? (NCHUNK - 1 - (int)blockIdx.x) : (int)blockIdx.x;
        const int q0 = chunk * 64;
        const int nT = chunk + 1;

        __syncthreads();   // previous chunk fully done with smem

        // ---- Q A-fragments, register resident for the chunk ----
        uint32_t qa[8][4];
        {
            const float* qp  = g_q + (bT + q0 + mw * 16 + g) * HD;
            const float* qp8 = qp + 8 * HD;
            #pragma unroll
            for (int tk = 0; tk < 8; tk++) {
                qa[tk][0] = f2tf(qp [tk * 8 + t]     * SCALE);
                qa[tk][1] = f2tf(qp8[tk * 8 + t]     * SCALE);
                qa[tk][2] = f2tf(qp [tk * 8 + t + 4] * SCALE);
                qa[tk][3] = f2tf(qp8[tk * 8 + t + 4] * SCALE);
            }
        }

        // ---- stage tile 0 ----
        {
            const float* ks = g_kF + (bT + 0) * 64;
            #pragma unroll
            for (int it = 0; it < 4; it++) {
                int f4 = it * 256 + tid;
                uint32_t d = (uint32_t)__cvta_generic_to_shared(sm + SK0 + f4 * 4);
                CPA16(d, ks + f4 * 4);
            }
            #pragma unroll
            for (int it = 0; it < 4; it++) {
                int f = it * 256 + tid;
                int r = f >> 4, c4 = (f & 15) * 4;
                uint32_t d = (uint32_t)__cvta_generic_to_shared(sm + SV0 + r * VP + c4);
                CPA16(d, g_v + (bT + r) * HD + c4);
            }
            CPA_COMMIT();
        }
        CPA_WAIT0();
        __syncthreads();

        float of[4][4] = {};
        float rs_lo = 0.0f, rs_hi = 0.0f;

        #pragma unroll 1
        for (int tt = 0; tt < nT; tt++) {
            const int j0 = tt * 64;
            const float* Kc = sm + ((tt & 1) ? SK1 : SK0);
            const float* Vc = sm + ((tt & 1) ? SV1 : SV0);

            // prefetch next tile into the other buffer
            if (tt + 1 < nT) {
                float* Kn = sm + ((tt & 1) ? SK0 : SK1);
                float* Vn = sm + ((tt & 1) ? SV0 : SV1);
                const float* ks = g_kF + (bT + j0 + 64) * 64;
                #pragma unroll
                for (int it = 0; it < 4; it++) {
                    int f4 = it * 256 + tid;
                    uint32_t d = (uint32_t)__cvta_generic_to_shared(Kn + f4 * 4);
                    CPA16(d, ks + f4 * 4);
                }
                #pragma unroll
                for (int it = 0; it < 4; it++) {
                    int f = it * 256 + tid;
                    int r = f >> 4, c4 = (f & 15) * 4;
                    uint32_t d = (uint32_t)__cvta_generic_to_shared(Vn + r * VP + c4);
                    CPA16(d, g_v + (bT + j0 + 64 + r) * HD + c4);
                }
                CPA_COMMIT();
            }

            // ---- S = Q K^T on tensor pipe ----
            float sc[4][4] = {};
            #pragma unroll
            for (int tk = 0; tk < 8; tk++) {
                #pragma unroll
                for (int ns = 0; ns < 4; ns++) {
                    float2 kb = *(const float2*)
                        &Kc[((tk * 8 + nw * 4 + ns) * 32 + lane) * 2];
                    mma8(sc[ns], qa[tk],
                         __float_as_uint(kb.x), __float_as_uint(kb.y));
                }
            }

            // ---- ALiBi + causal + exp, stage P (tf32-rounded) ----
            const bool diag = (tt == nT - 1);
            const int qrLo = q0 + mw * 16 + g;
            const int qrHi = qrLo + 8;
            #pragma unroll
            for (int ns = 0; ns < 4; ns++) {
                const int k0c = j0 + nw * 32 + ns * 8 + 2 * t;
                float p0 = __expf(sc[ns][0] + SLOPE * (float)(k0c     - qrLo));
                float p1 = __expf(sc[ns][1] + SLOPE * (float)(k0c + 1 - qrLo));
                float p2 = __expf(sc[ns][2] + SLOPE * (float)(k0c     - qrHi));
                float p3 = __expf(sc[ns][3] + SLOPE * (float)(k0c + 1 - qrHi));
                if (diag) {
                    if (k0c     > qrLo) p0 = 0.0f;
                    if (k0c + 1 > qrLo) p1 = 0.0f;
                    if (k0c     > qrHi) p2 = 0.0f;
                    if (k0c + 1 > qrHi) p3 = 0.0f;
                }
                rs_lo += p0 + p1;
                rs_hi += p2 + p3;
                float* Pr = sm + SPP + (mw * 16 + g) * PP + nw * 32 + ns * 8 + 2 * t;
                *(float2*)Pr            = make_float2(tf32f(p0), tf32f(p1));
                *(float2*)(Pr + 8 * PP) = make_float2(tf32f(p2), tf32f(p3));
            }
            __syncthreads();   // P visible to all warps

            // ---- O += P V on tensor pipe ----
            #pragma unroll
            for (int pk = 0; pk < 8; pk++) {
                uint32_t pa[4];
                const float* Pb = sm + SPP + (mw * 16 + g) * PP + pk * 8 + t;
                pa[0] = __float_as_uint(Pb[0]);
                pa[1] = __float_as_uint(Pb[8 * PP]);
                pa[2] = __float_as_uint(Pb[4]);
                pa[3] = __float_as_uint(Pb[8 * PP + 4]);
                const float* Vb = Vc + (pk * 8 + t) * VP + nw * 32 + g;
                #pragma unroll
                for (int ns = 0; ns < 4; ns++) {
                    uint32_t vb0 = __float_as_uint(Vb[ns * 8]);
                    uint32_t vb1 = __float_as_uint(Vb[ns * 8 + 4 * VP]);
                    mma8(of[ns], pa, vb0, vb1);
                }
            }

            CPA_WAIT0();
            __syncthreads();   // next tile staged; P free for rewrite
        }

        // ---- epilogue: row sums, normalize, store ----
        rs_lo += __shfl_xor_sync(0xffffffffu, rs_lo, 1);
        rs_lo += __shfl_xor_sync(0xffffffffu, rs_lo, 2);
        rs_hi += __shfl_xor_sync(0xffffffffu, rs_hi, 1);
        rs_hi += __shfl_xor_sync(0xffffffffu, rs_hi, 2);
        if (t == 0) {
            sm[SLS + nw * 64 + mw * 16 + g]     = rs_lo;
            sm[SLS + nw * 64 + mw * 16 + g + 8] = rs_hi;
        }
        __syncthreads();
        const float invLo = 1.0f / (sm[SLS + mw * 16 + g]     + sm[SLS + 64 + mw * 16 + g]);
        const float invHi = 1.0f / (sm[SLS + mw * 16 + g + 8] + sm[SLS + 64 + mw * 16 + g + 8]);
        #pragma unroll
        for (int ns = 0; ns < 4; ns++) {
            float* orow = out + (bT + q0 + mw * 16 + g) * HD + nw * 32 + ns * 8 + 2 * t;
            *(float2*)orow            = make_float2(of[ns][0] * invLo, of[ns][1] * invLo);
            *(float2*)(orow + 8 * HD) = make_float2(of[ns][2] * invHi, of[ns][3] * invHi);
        }
    }
}

// -------------------------------------------------------------------------
extern "C" void kernel_launch(void* const* d_in, const int* in_sizes, int n_in,
                              void* d_out, int out_size)
{
    const float* x  = (const float*)d_in[0];
    const float* wq = (const float*)d_in[1];
    const float* wk = (const float*)d_in[2];
    const float* wv = (const float*)d_in[3];
    float* out = (float*)d_out;

    (void)in_sizes; (void)n_in; (void)out_size;

    cudaFuncSetAttribute(attn_kernel,
                         cudaFuncAttributeMaxDynamicSharedMemorySize, ATTN_SMEM);

    dim3 tgrid(CEMB * HD / 256, 3);
    wtrans_kernel<<<tgrid, 256>>>(wq, wk, wv);

    dim3 ggrid(MTOT / QBM, 1, 3);
    qkv_gemm<<<ggrid, 256>>>(x);

    dim3 agrid(NCHUNK / 2, BATCH);
    attn_kernel<<<agrid, 256, ATTN_SMEM>>>(out);
}

// round 6
// speedup vs baseline: 12.8543x; 1.4907x over previous
#include <cuda_runtime.h>
#include <cuda_bf16.h>
#include <cstdint>

// Problem constants
#define BATCH 4
#define TSEQ  4096
#define CEMB  1024
#define HD    64
#define MTOT  (BATCH * TSEQ)          // 16384 tokens

__device__ float g_q [MTOT * HD];     // [token][d] row-major (fp32)
__device__ float g_kF[MTOT * HD];     // B-fragment-major per 64-key tile (tf32 bits)
__device__ float g_v [MTOT * HD];     // [token][d] row-major (tf32-rounded)

// ---- tf32 / mma helpers --------------------------------------------------
__device__ __forceinline__ uint32_t f2tf(float f) {
    uint32_t u;
    asm("cvt.rna.tf32.f32 %0, %1;" : "=r"(u) : "f"(f));
    return u;
}
__device__ __forceinline__ float tf32f(float f) { return __uint_as_float(f2tf(f)); }

__device__ __forceinline__ void mma8(float c[4], const uint32_t a[4],
                                     uint32_t b0, uint32_t b1) {
    asm volatile(
        "mma.sync.aligned.m16n8k8.row.col.f32.tf32.tf32.f32 "
        "{%0,%1,%2,%3}, {%4,%5,%6,%7}, {%8,%9}, {%0,%1,%2,%3};"
        : "+f"(c[0]), "+f"(c[1]), "+f"(c[2]), "+f"(c[3])
        : "r"(a[0]), "r"(a[1]), "r"(a[2]), "r"(a[3]), "r"(b0), "r"(b1));
}

__device__ __forceinline__ void mma16(float c[4], const uint32_t a[4],
                                      const uint32_t b[2]) {
    asm volatile(
        "mma.sync.aligned.m16n8k16.row.col.f32.bf16.bf16.f32 "
        "{%0,%1,%2,%3}, {%4,%5,%6,%7}, {%8,%9}, {%0,%1,%2,%3};"
        : "+f"(c[0]), "+f"(c[1]), "+f"(c[2]), "+f"(c[3])
        : "r"(a[0]), "r"(a[1]), "r"(a[2]), "r"(a[3]), "r"(b[0]), "r"(b[1]));
}

#define CPA16(dst_s32, src) \
    asm volatile("cp.async.ca.shared.global [%0], [%1], 16;" :: "r"(dst_s32), "l"(src))
#define CPA_COMMIT() asm volatile("cp.async.commit_group;")
#define CPA_WAIT0()  asm volatile("cp.async.wait_group 0;" ::: "memory")

// pack two bf16 into u32 (a in low 16 bits)
__device__ __forceinline__ uint32_t packbf(__nv_bfloat16 a, __nv_bfloat16 b) {
    __nv_bfloat162 v(a, b);
    return *reinterpret_cast<uint32_t*>(&v);
}
// split pair of floats into hi/lo bf16 pairs
__device__ __forceinline__ void split2(float f0, float f1,
                                       uint32_t& h, uint32_t& l) {
    __nv_bfloat16 h0 = __float2bfloat16(f0);
    __nv_bfloat16 h1 = __float2bfloat16(f1);
    __nv_bfloat16 l0 = __float2bfloat16(f0 - __bfloat162float(h0));
    __nv_bfloat16 l1 = __float2bfloat16(f1 - __bfloat162float(h1));
    h = packbf(h0, h1);
    l = packbf(l0, l1);
}

// -------------------------------------------------------------------------
// QKV projection on tensor cores: bf16 mma with 3-term error split.
// M=16384(tiles of 128), N=64, K=1024 (BK=64). 256 threads = 8 warps
// arranged 4(m) x 2(n): warp tile 32x32. blockIdx.z selects q/k/v.
// -------------------------------------------------------------------------
#define KST 72   // smem k-stride in bf16 elements

#define SX_HI 0
#define SX_LO (128 * KST)
#define SW_HI (2 * 128 * KST)
#define SW_LO (SW_HI + 64 * KST)
#define QKV_SMEM_HALFS (SW_LO + 64 * KST)
#define QKV_SMEM ((int)(QKV_SMEM_HALFS * sizeof(__nv_bfloat16)))  // 55,296 B

__global__ __launch_bounds__(256, 2) void qkv_gemm(
    const float* __restrict__ x,
    const float* __restrict__ wq,
    const float* __restrict__ wk,
    const float* __restrict__ wv)
{
    extern __shared__ __nv_bfloat16 smh[];
    const int z = blockIdx.z;
    const float* w = (z == 0) ? wq : (z == 1) ? wk : wv;

    const int m0   = blockIdx.x * 128;
    const int tid  = threadIdx.x;
    const int lane = tid & 31;
    const int wid  = tid >> 5;
    const int mw   = wid >> 1;    // 0..3
    const int nw   = wid & 1;     // 0..1
    const int g    = lane >> 2;
    const int t    = lane & 3;

    float c[2][4][4] = {};

    for (int k0 = 0; k0 < CEMB; k0 += 64) {
        __syncthreads();
        // ---- stage x tile 128x64 (fp32 -> hi/lo bf16) ----
        #pragma unroll
        for (int it = 0; it < 8; it++) {
            int f  = tid + it * 256;
            int r  = f >> 4;
            int c4 = (f & 15) * 4;
            float4 v = *(const float4*)&x[(size_t)(m0 + r) * CEMB + k0 + c4];
            uint32_t h01, l01, h23, l23;
            split2(v.x, v.y, h01, l01);
            split2(v.z, v.w, h23, l23);
            uint32_t* ph = (uint32_t*)&smh[SX_HI + r * KST + c4];
            uint32_t* pl = (uint32_t*)&smh[SX_LO + r * KST + c4];
            ph[0] = h01; ph[1] = h23;
            pl[0] = l01; pl[1] = l23;
        }
        // ---- stage w tile 64x64 ----
        #pragma unroll
        for (int it = 0; it < 4; it++) {
            int f  = tid + it * 256;
            int r  = f >> 4;
            int c4 = (f & 15) * 4;
            float4 v = *(const float4*)&w[(size_t)r * CEMB + k0 + c4];
            uint32_t h01, l01, h23, l23;
            split2(v.x, v.y, h01, l01);
            split2(v.z, v.w, h23, l23);
            uint32_t* ph = (uint32_t*)&smh[SW_HI + r * KST + c4];
            uint32_t* pl = (uint32_t*)&smh[SW_LO + r * KST + c4];
            ph[0] = h01; ph[1] = h23;
            pl[0] = l01; pl[1] = l23;
        }
        __syncthreads();

        // ---- compute: 4 k16-steps ----
        #pragma unroll
        for (int s = 0; s < 4; s++) {
            const int kk = s * 16;
            uint32_t ah[2][4], al[2][4], bh[4][2], bl[4][2];
            #pragma unroll
            for (int mf = 0; mf < 2; mf++) {
                const int mr = mw * 32 + mf * 16 + g;
                const __nv_bfloat16* ph = &smh[SX_HI + mr * KST + kk + 2 * t];
                const __nv_bfloat16* pl = &smh[SX_LO + mr * KST + kk + 2 * t];
                ah[mf][0] = *(const uint32_t*)ph;
                ah[mf][1] = *(const uint32_t*)(ph + 8 * KST);
                ah[mf][2] = *(const uint32_t*)(ph + 8);
                ah[mf][3] = *(const uint32_t*)(ph + 8 * KST + 8);
                al[mf][0] = *(const uint32_t*)pl;
                al[mf][1] = *(const uint32_t*)(pl + 8 * KST);
                al[mf][2] = *(const uint32_t*)(pl + 8);
                al[mf][3] = *(const uint32_t*)(pl + 8 * KST + 8);
            }
            #pragma unroll
            for (int nf = 0; nf < 4; nf++) {
                const int nr = nw * 32 + nf * 8 + g;
                const __nv_bfloat16* ph = &smh[SW_HI + nr * KST + kk + 2 * t];
                const __nv_bfloat16* pl = &smh[SW_LO + nr * KST + kk + 2 * t];
                bh[nf][0] = *(const uint32_t*)ph;
                bh[nf][1] = *(const uint32_t*)(ph + 8);
                bl[nf][0] = *(const uint32_t*)pl;
                bl[nf][1] = *(const uint32_t*)(pl + 8);
            }
            #pragma unroll
            for (int mf = 0; mf < 2; mf++)
                #pragma unroll
                for (int nf = 0; nf < 4; nf++) {
                    mma16(c[mf][nf], ah[mf], bh[nf]);   // hi*hi
                    mma16(c[mf][nf], al[mf], bh[nf]);   // lo*hi
                    mma16(c[mf][nf], ah[mf], bl[nf]);   // hi*lo
                }
        }
    }

    // ---- epilogue ----
    if (z == 1) {
        // K -> B-fragment-major tf32 layout used by the attention kernel.
        // element (key,d): tile=key/64, n8=(key%64)/8, g=key%8, d8=d/8,
        // dm=d%8: addr = tile*4096 + (d8*8+n8)*64 + g*8 + (dm&3)*2 + (dm>>2)
        #pragma unroll
        for (int mf = 0; mf < 2; mf++)
            #pragma unroll
            for (int hi = 0; hi < 2; hi++) {
                const int key  = m0 + mw * 32 + mf * 16 + hi * 8 + g;
                const int tile = key >> 6;
                const int n8   = (key >> 3) & 7;
                float* tb = g_kF + (size_t)tile * 4096 + n8 * 64 + g * 8;
                #pragma unroll
                for (int nf = 0; nf < 4; nf++)
                    #pragma unroll
                    for (int jj = 0; jj < 2; jj++) {
                        const int d  = nw * 32 + nf * 8 + 2 * t + jj;
                        const int d8 = d >> 3, dm = d & 7;
                        tb[d8 * 512 + (dm & 3) * 2 + (dm >> 2)] =
                            tf32f(c[mf][nf][hi * 2 + jj]);
                    }
            }
    } else {
        float* dst = (z == 0) ? g_q : g_v;
        #pragma unroll
        for (int mf = 0; mf < 2; mf++) {
            const int r0 = m0 + mw * 32 + mf * 16 + g;
            #pragma unroll
            for (int nf = 0; nf < 4; nf++) {
                const int n = nw * 32 + nf * 8 + 2 * t;
                float v0 = c[mf][nf][0], v1 = c[mf][nf][1];
                float v2 = c[mf][nf][2], v3 = c[mf][nf][3];
                if (z == 2) { v0 = tf32f(v0); v1 = tf32f(v1);
                              v2 = tf32f(v2); v3 = tf32f(v3); }
                *(float2*)&dst[(size_t)r0 * HD + n]       = make_float2(v0, v1);
                *(float2*)&dst[(size_t)(r0 + 8) * HD + n] = make_float2(v2, v3);
            }
        }
    }
}

// -------------------------------------------------------------------------
// Flash attention on tensor cores (mma.sync tf32) — unchanged from R5.
// -------------------------------------------------------------------------
#define NCHUNK (TSEQ / 64)
#define VP 72
#define PP 68
#define SK0 0
#define SK1 4096
#define SV0 8192
#define SV1 (SV0 + 64 * VP)
#define SPP (SV1 + 64 * VP)
#define SLS (SPP + 64 * PP)
#define ATTN_SMEM ((SLS + 128) * 4)   // 87,552 B

__global__ __launch_bounds__(256) void attn_kernel(float* __restrict__ out)
{
    constexpr float SCALE = 0.03125f;
    constexpr float SLOPE = 0.70710678118654752f;

    extern __shared__ float sm[];
    const int b    = blockIdx.y;
    const size_t bT = (size_t)b * TSEQ;
    const int tid  = threadIdx.x;
    const int lane = tid & 31;
    const int wid  = tid >> 5;
    const int mw   = wid >> 1;
    const int nw   = wid & 1;
    const int g    = lane >> 2;
    const int t    = lane & 3;

    #pragma unroll 1
    for (int half = 0; half < 2; half++) {
        const int chunk = half ? (NCHUNK - 1 - (int)blockIdx.x) : (int)blockIdx.x;
        const int q0 = chunk * 64;
        const int nT = chunk + 1;

        __syncthreads();

        uint32_t qa[8][4];
        {
            const float* qp  = g_q + (bT + q0 + mw * 16 + g) * HD;
            const float* qp8 = qp + 8 * HD;
            #pragma unroll
            for (int tk = 0; tk < 8; tk++) {
                qa[tk][0] = f2tf(qp [tk * 8 + t]     * SCALE);
                qa[tk][1] = f2tf(qp8[tk * 8 + t]     * SCALE);
                qa[tk][2] = f2tf(qp [tk * 8 + t + 4] * SCALE);
                qa[tk][3] = f2tf(qp8[tk * 8 + t + 4] * SCALE);
            }
        }

        {
            const float* ks = g_kF + (bT + 0) * 64;
            #pragma unroll
            for (int it = 0; it < 4; it++) {
                int f4 = it * 256 + tid;
                uint32_t d = (uint32_t)__cvta_generic_to_shared(sm + SK0 + f4 * 4);
                CPA16(d, ks + f4 * 4);
            }
            #pragma unroll
            for (int it = 0; it < 4; it++) {
                int f = it * 256 + tid;
                int r = f >> 4, c4 = (f & 15) * 4;
                uint32_t d = (uint32_t)__cvta_generic_to_shared(sm + SV0 + r * VP + c4);
                CPA16(d, g_v + (bT + r) * HD + c4);
            }
            CPA_COMMIT();
        }
        CPA_WAIT0();
        __syncthreads();

        float of[4][4] = {};
        float rs_lo = 0.0f, rs_hi = 0.0f;

        #pragma unroll 1
        for (int tt = 0; tt < nT; tt++) {
            const int j0 = tt * 64;
            const float* Kc = sm + ((tt & 1) ? SK1 : SK0);
            const float* Vc = sm + ((tt & 1) ? SV1 : SV0);

            if (tt + 1 < nT) {
                float* Kn = sm + ((tt & 1) ? SK0 : SK1);
                float* Vn = sm + ((tt & 1) ? SV0 : SV1);
                const float* ks = g_kF + (bT + j0 + 64) * 64;
                #pragma unroll
                for (int it = 0; it < 4; it++) {
                    int f4 = it * 256 + tid;
                    uint32_t d = (uint32_t)__cvta_generic_to_shared(Kn + f4 * 4);
                    CPA16(d, ks + f4 * 4);
                }
                #pragma unroll
                for (int it = 0; it < 4; it++) {
                    int f = it * 256 + tid;
                    int r = f >> 4, c4 = (f & 15) * 4;
                    uint32_t d = (uint32_t)__cvta_generic_to_shared(Vn + r * VP + c4);
                    CPA16(d, g_v + (bT + j0 + 64 + r) * HD + c4);
                }
                CPA_COMMIT();
            }

            float sc[4][4] = {};
            #pragma unroll
            for (int tk = 0; tk < 8; tk++) {
                #pragma unroll
                for (int ns = 0; ns < 4; ns++) {
                    float2 kb = *(const float2*)
                        &Kc[((tk * 8 + nw * 4 + ns) * 32 + lane) * 2];
                    mma8(sc[ns], qa[tk],
                         __float_as_uint(kb.x), __float_as_uint(kb.y));
                }
            }

            const bool diag = (tt == nT - 1);
            const int qrLo = q0 + mw * 16 + g;
            const int qrHi = qrLo + 8;
            #pragma unroll
            for (int ns = 0; ns < 4; ns++) {
                const int k0c = j0 + nw * 32 + ns * 8 + 2 * t;
                float p0 = __expf(sc[ns][0] + SLOPE * (float)(k0c     - qrLo));
                float p1 = __expf(sc[ns][1] + SLOPE * (float)(k0c + 1 - qrLo));
                float p2 = __expf(sc[ns][2] + SLOPE * (float)(k0c     - qrHi));
                float p3 = __expf(sc[ns][3] + SLOPE * (float)(k0c + 1 - qrHi));
                if (diag) {
                    if (k0c     > qrLo) p0 = 0.0f;
                    if (k0c + 1 > qrLo) p1 = 0.0f;
                    if (k0c     > qrHi) p2 = 0.0f;
                    if (k0c + 1 > qrHi) p3 = 0.0f;
                }
                rs_lo += p0 + p1;
                rs_hi += p2 + p3;
                float* Pr = sm + SPP + (mw * 16 + g) * PP + nw * 32 + ns * 8 + 2 * t;
                *(float2*)Pr            = make_float2(tf32f(p0), tf32f(p1));
                *(float2*)(Pr + 8 * PP) = make_float2(tf32f(p2), tf32f(p3));
            }
            __syncthreads();

            #pragma unroll
            for (int pk = 0; pk < 8; pk++) {
                uint32_t pa[4];
                const float* Pb = sm + SPP + (mw * 16 + g) * PP + pk * 8 + t;
                pa[0] = __float_as_uint(Pb[0]);
                pa[1] = __float_as_uint(Pb[8 * PP]);
                pa[2] = __float_as_uint(Pb[4]);
                pa[3] = __float_as_uint(Pb[8 * PP + 4]);
                const float* Vb = Vc + (pk * 8 + t) * VP + nw * 32 + g;
                #pragma unroll
                for (int ns = 0; ns < 4; ns++) {
                    uint32_t vb0 = __float_as_uint(Vb[ns * 8]);
                    uint32_t vb1 = __float_as_uint(Vb[ns * 8 + 4 * VP]);
                    mma8(of[ns], pa, vb0, vb1);
                }
            }

            CPA_WAIT0();
            __syncthreads();
        }

        rs_lo += __shfl_xor_sync(0xffffffffu, rs_lo, 1);
        rs_lo += __shfl_xor_sync(0xffffffffu, rs_lo, 2);
        rs_hi += __shfl_xor_sync(0xffffffffu, rs_hi, 1);
        rs_hi += __shfl_xor_sync(0xffffffffu, rs_hi, 2);
        if (t == 0) {
            sm[SLS + nw * 64 + mw * 16 + g]     = rs_lo;
            sm[SLS + nw * 64 + mw * 16 + g + 8] = rs_hi;
        }
        __syncthreads();
        const float invLo = 1.0f / (sm[SLS + mw * 16 + g]     + sm[SLS + 64 + mw * 16 + g]);
        const float invHi = 1.0f / (sm[SLS + mw * 16 + g + 8] + sm[SLS + 64 + mw * 16 + g + 8]);
        #pragma unroll
        for (int ns = 0; ns < 4; ns++) {
            float* orow = out + (bT + q0 + mw * 16 + g) * HD + nw * 32 + ns * 8 + 2 * t;
            *(float2*)orow            = make_float2(of[ns][0] * invLo, of[ns][1] * invLo);
            *(float2*)(orow + 8 * HD) = make_float2(of[ns][2] * invHi, of[ns][3] * invHi);
        }
    }
}

// -------------------------------------------------------------------------
extern "C" void kernel_launch(void* const* d_in, const int* in_sizes, int n_in,
                              void* d_out, int out_size)
{
    const float* x  = (const float*)d_in[0];
    const float* wq = (const float*)d_in[1];
    const float* wk = (const float*)d_in[2];
    const float* wv = (const float*)d_in[3];
    float* out = (float*)d_out;

    (void)in_sizes; (void)n_in; (void)out_size;

    cudaFuncSetAttribute(qkv_gemm,
                         cudaFuncAttributeMaxDynamicSharedMemorySize, QKV_SMEM);
    cudaFuncSetAttribute(attn_kernel,
                         cudaFuncAttributeMaxDynamicSharedMemorySize, ATTN_SMEM);

    dim3 ggrid(MTOT / 128, 1, 3);   // 128 x 1 x 3
    qkv_gemm<<<ggrid, 256, QKV_SMEM>>>(x, wq, wk, wv);

    dim3 agrid(NCHUNK / 2, BATCH);  // 32 x 4
    attn_kernel<<<agrid, 256, ATTN_SMEM>>>(out);
}

// round 11
// speedup vs baseline: 12.8754x; 1.0016x over previous
#include <cuda_runtime.h>
#include <cuda_bf16.h>
#include <cstdint>

// Problem constants
#define BATCH 4
#define TSEQ  4096
#define CEMB  1024
#define HD    64
#define MTOT  (BATCH * TSEQ)          // 16384 tokens

__device__ float g_q [MTOT * HD];     // [token][d] row-major (fp32)
__device__ float g_kF[MTOT * HD];     // B-fragment-major per 64-key tile (tf32 bits)
__device__ float g_v [MTOT * HD];     // [token][d] row-major (tf32-rounded)
__device__ float g_oP[2 * MTOT * HD]; // split-K partial O (unnormalized)
__device__ float g_lP[2 * MTOT];      // split-K partial row sums

// ---- tf32 / mma helpers --------------------------------------------------
__device__ __forceinline__ uint32_t f2tf(float f) {
    uint32_t u;
    asm("cvt.rna.tf32.f32 %0, %1;" : "=r"(u) : "f"(f));
    return u;
}
__device__ __forceinline__ float tf32f(float f) { return __uint_as_float(f2tf(f)); }

__device__ __forceinline__ void mma8(float c[4], const uint32_t a[4],
                                     uint32_t b0, uint32_t b1) {
    asm volatile(
        "mma.sync.aligned.m16n8k8.row.col.f32.tf32.tf32.f32 "
        "{%0,%1,%2,%3}, {%4,%5,%6,%7}, {%8,%9}, {%0,%1,%2,%3};"
        : "+f"(c[0]), "+f"(c[1]), "+f"(c[2]), "+f"(c[3])
        : "r"(a[0]), "r"(a[1]), "r"(a[2]), "r"(a[3]), "r"(b0), "r"(b1));
}

__device__ __forceinline__ void mma16(float c[4], const uint32_t a[4],
                                      const uint32_t b[2]) {
    asm volatile(
        "mma.sync.aligned.m16n8k16.row.col.f32.bf16.bf16.f32 "
        "{%0,%1,%2,%3}, {%4,%5,%6,%7}, {%8,%9}, {%0,%1,%2,%3};"
        : "+f"(c[0]), "+f"(c[1]), "+f"(c[2]), "+f"(c[3])
        : "r"(a[0]), "r"(a[1]), "r"(a[2]), "r"(a[3]), "r"(b[0]), "r"(b[1]));
}

#define CPA16(dst_s32, src) \
    asm volatile("cp.async.ca.shared.global [%0], [%1], 16;" :: "r"(dst_s32), "l"(src))
#define CPA_COMMIT() asm volatile("cp.async.commit_group;")
#define CPA_WAIT0()  asm volatile("cp.async.wait_group 0;" ::: "memory")

// pack two bf16 into u32 (a in low 16 bits)
__device__ __forceinline__ uint32_t packbf(__nv_bfloat16 a, __nv_bfloat16 b) {
    __nv_bfloat162 v(a, b);
    return *reinterpret_cast<uint32_t*>(&v);
}
// split pair of floats into hi/lo bf16 pairs
__device__ __forceinline__ void split2(float f0, float f1,
                                       uint32_t& h, uint32_t& l) {
    __nv_bfloat16 h0 = __float2bfloat16(f0);
    __nv_bfloat16 h1 = __float2bfloat16(f1);
    __nv_bfloat16 l0 = __float2bfloat16(f0 - __bfloat162float(h0));
    __nv_bfloat16 l1 = __float2bfloat16(f1 - __bfloat162float(h1));
    h = packbf(h0, h1);
    l = packbf(l0, l1);
}

// -------------------------------------------------------------------------
// QKV projection on tensor cores: bf16 mma with 3-term error split.
// (unchanged from R5)
// -------------------------------------------------------------------------
#define KST 72   // smem k-stride in bf16 elements

#define SX_HI 0
#define SX_LO (128 * KST)
#define SW_HI (2 * 128 * KST)
#define SW_LO (SW_HI + 64 * KST)
#define QKV_SMEM_HALFS (SW_LO + 64 * KST)
#define QKV_SMEM ((int)(QKV_SMEM_HALFS * sizeof(__nv_bfloat16)))  // 55,296 B

__global__ __launch_bounds__(256, 2) void qkv_gemm(
    const float* __restrict__ x,
    const float* __restrict__ wq,
    const float* __restrict__ wk,
    const float* __restrict__ wv)
{
    extern __shared__ __nv_bfloat16 smh[];
    const int z = blockIdx.z;
    const float* w = (z == 0) ? wq : (z == 1) ? wk : wv;

    const int m0   = blockIdx.x * 128;
    const int tid  = threadIdx.x;
    const int lane = tid & 31;
    const int wid  = tid >> 5;
    const int mw   = wid >> 1;
    const int nw   = wid & 1;
    const int g    = lane >> 2;
    const int t    = lane & 3;

    float c[2][4][4] = {};

    for (int k0 = 0; k0 < CEMB; k0 += 64) {
        __syncthreads();
        #pragma unroll
        for (int it = 0; it < 8; it++) {
            int f  = tid + it * 256;
            int r  = f >> 4;
            int c4 = (f & 15) * 4;
            float4 v = *(const float4*)&x[(size_t)(m0 + r) * CEMB + k0 + c4];
            uint32_t h01, l01, h23, l23;
            split2(v.x, v.y, h01, l01);
            split2(v.z, v.w, h23, l23);
            uint32_t* ph = (uint32_t*)&smh[SX_HI + r * KST + c4];
            uint32_t* pl = (uint32_t*)&smh[SX_LO + r * KST + c4];
            ph[0] = h01; ph[1] = h23;
            pl[0] = l01; pl[1] = l23;
        }
        #pragma unroll
        for (int it = 0; it < 4; it++) {
            int f  = tid + it * 256;
            int r  = f >> 4;
            int c4 = (f & 15) * 4;
            float4 v = *(const float4*)&w[(size_t)r * CEMB + k0 + c4];
            uint32_t h01, l01, h23, l23;
            split2(v.x, v.y, h01, l01);
            split2(v.z, v.w, h23, l23);
            uint32_t* ph = (uint32_t*)&smh[SW_HI + r * KST + c4];
            uint32_t* pl = (uint32_t*)&smh[SW_LO + r * KST + c4];
            ph[0] = h01; ph[1] = h23;
            pl[0] = l01; pl[1] = l23;
        }
        __syncthreads();

        #pragma unroll
        for (int s = 0; s < 4; s++) {
            const int kk = s * 16;
            uint32_t ah[2][4], al[2][4], bh[4][2], bl[4][2];
            #pragma unroll
            for (int mf = 0; mf < 2; mf++) {
                const int mr = mw * 32 + mf * 16 + g;
                const __nv_bfloat16* ph = &smh[SX_HI + mr * KST + kk + 2 * t];
                const __nv_bfloat16* pl = &smh[SX_LO + mr * KST + kk + 2 * t];
                ah[mf][0] = *(const uint32_t*)ph;
                ah[mf][1] = *(const uint32_t*)(ph + 8 * KST);
                ah[mf][2] = *(const uint32_t*)(ph + 8);
                ah[mf][3] = *(const uint32_t*)(ph + 8 * KST + 8);
                al[mf][0] = *(const uint32_t*)pl;
                al[mf][1] = *(const uint32_t*)(pl + 8 * KST);
                al[mf][2] = *(const uint32_t*)(pl + 8);
                al[mf][3] = *(const uint32_t*)(pl + 8 * KST + 8);
            }
            #pragma unroll
            for (int nf = 0; nf < 4; nf++) {
                const int nr = nw * 32 + nf * 8 + g;
                const __nv_bfloat16* ph = &smh[SW_HI + nr * KST + kk + 2 * t];
                const __nv_bfloat16* pl = &smh[SW_LO + nr * KST + kk + 2 * t];
                bh[nf][0] = *(const uint32_t*)ph;
                bh[nf][1] = *(const uint32_t*)(ph + 8);
                bl[nf][0] = *(const uint32_t*)pl;
                bl[nf][1] = *(const uint32_t*)(pl + 8);
            }
            #pragma unroll
            for (int mf = 0; mf < 2; mf++)
                #pragma unroll
                for (int nf = 0; nf < 4; nf++) {
                    mma16(c[mf][nf], ah[mf], bh[nf]);
                    mma16(c[mf][nf], al[mf], bh[nf]);
                    mma16(c[mf][nf], ah[mf], bl[nf]);
                }
        }
    }

    if (z == 1) {
        #pragma unroll
        for (int mf = 0; mf < 2; mf++)
            #pragma unroll
            for (int hi = 0; hi < 2; hi++) {
                const int key  = m0 + mw * 32 + mf * 16 + hi * 8 + g;
                const int tile = key >> 6;
                const int n8   = (key >> 3) & 7;
                float* tb = g_kF + (size_t)tile * 4096 + n8 * 64 + g * 8;
                #pragma unroll
                for (int nf = 0; nf < 4; nf++)
                    #pragma unroll
                    for (int jj = 0; jj < 2; jj++) {
                        const int d  = nw * 32 + nf * 8 + 2 * t + jj;
                        const int d8 = d >> 3, dm = d & 7;
                        tb[d8 * 512 + (dm & 3) * 2 + (dm >> 2)] =
                            tf32f(c[mf][nf][hi * 2 + jj]);
                    }
            }
    } else {
        float* dst = (z == 0) ? g_q : g_v;
        #pragma unroll
        for (int mf = 0; mf < 2; mf++) {
            const int r0 = m0 + mw * 32 + mf * 16 + g;
            #pragma unroll
            for (int nf = 0; nf < 4; nf++) {
                const int n = nw * 32 + nf * 8 + 2 * t;
                float v0 = c[mf][nf][0], v1 = c[mf][nf][1];
                float v2 = c[mf][nf][2], v3 = c[mf][nf][3];
                if (z == 2) { v0 = tf32f(v0); v1 = tf32f(v1);
                              v2 = tf32f(v2); v3 = tf32f(v3); }
                *(float2*)&dst[(size_t)r0 * HD + n]       = make_float2(v0, v1);
                *(float2*)&dst[(size_t)(r0 + 8) * HD + n] = make_float2(v2, v3);
            }
        }
    }
}

// -------------------------------------------------------------------------
// Flash attention on tensor cores, split-K across blockIdx.z (tile parity).
// Fixed-reference softmax -> partials combine additively. Single-buffered
// K/V/P (52.7 KB smem) -> 2 CTAs/SM. Partial O and l written to scratch;
// combine_kernel normalizes.
// -------------------------------------------------------------------------
#define NCHUNK (TSEQ / 64)
#define VP 72
#define PP 68
#define SK  0
#define SV  4096
#define SPP (SV + 64 * VP)                 // 8704
#define SLS (SPP + 64 * PP)                // 13056
#define ATTN_SMEM ((SLS + 128) * 4)        // 52,736 B

__global__ __launch_bounds__(256, 2) void attn_kernel()
{
    constexpr float SCALE = 0.03125f;
    constexpr float SLOPE = 0.70710678118654752f;

    extern __shared__ float sm[];
    const int b    = blockIdx.y;
    const int sz   = blockIdx.z;           // tile parity 0/1
    const size_t bT = (size_t)b * TSEQ;
    const int tid  = threadIdx.x;
    const int lane = tid & 31;
    const int wid  = tid >> 5;
    const int mw   = wid >> 1;
    const int nw   = wid & 1;
    const int g    = lane >> 2;
    const int t    = lane & 3;

    float* oP = g_oP + (size_t)sz * MTOT * HD;
    float* lP = g_lP + (size_t)sz * MTOT;

    #pragma unroll 1
    for (int half = 0; half < 2; half++) {
        const int chunk = half ? (NCHUNK - 1 - (int)blockIdx.x) : (int)blockIdx.x;
        const int q0 = chunk * 64;
        const int nT = chunk + 1;

        __syncthreads();   // previous chunk fully done with smem

        // ---- Q A-fragments, register resident for the chunk ----
        uint32_t qa[8][4];
        {
            const float* qp  = g_q + (bT + q0 + mw * 16 + g) * HD;
            const float* qp8 = qp + 8 * HD;
            #pragma unroll
            for (int tk = 0; tk < 8; tk++) {
                qa[tk][0] = f2tf(qp [tk * 8 + t]     * SCALE);
                qa[tk][1] = f2tf(qp8[tk * 8 + t]     * SCALE);
                qa[tk][2] = f2tf(qp [tk * 8 + t + 4] * SCALE);
                qa[tk][3] = f2tf(qp8[tk * 8 + t + 4] * SCALE);
            }
        }

        float of[4][4] = {};
        float rs_lo = 0.0f, rs_hi = 0.0f;

        #pragma unroll 1
        for (int tt = sz; tt < nT; tt += 2) {
            const int j0 = tt * 64;

            // ---- stage K/V tile (single buffer) ----
            {
                const float* ks = g_kF + (bT + j0) * 64;
                #pragma unroll
                for (int it = 0; it < 4; it++) {
                    int f4 = it * 256 + tid;
                    uint32_t d = (uint32_t)__cvta_generic_to_shared(sm + SK + f4 * 4);
                    CPA16(d, ks + f4 * 4);
                }
                #pragma unroll
                for (int it = 0; it < 4; it++) {
                    int f = it * 256 + tid;
                    int r = f >> 4, c4 = (f & 15) * 4;
                    uint32_t d = (uint32_t)__cvta_generic_to_shared(sm + SV + r * VP + c4);
                    CPA16(d, g_v + (bT + j0 + r) * HD + c4);
                }
                CPA_COMMIT();
            }
            CPA_WAIT0();
            __syncthreads();   // tile staged

            // ---- S = Q K^T ----
            float sc[4][4] = {};
            #pragma unroll
            for (int tk = 0; tk < 8; tk++) {
                #pragma unroll
                for (int ns = 0; ns < 4; ns++) {
                    float2 kb = *(const float2*)
                        &sm[SK + ((tk * 8 + nw * 4 + ns) * 32 + lane) * 2];
                    mma8(sc[ns], qa[tk],
                         __float_as_uint(kb.x), __float_as_uint(kb.y));
                }
            }

            // ---- ALiBi + causal + exp, stage P ----
            const bool diag = (tt == nT - 1);
            const int qrLo = q0 + mw * 16 + g;
            const int qrHi = qrLo + 8;
            #pragma unroll
            for (int ns = 0; ns < 4; ns++) {
                const int k0c = j0 + nw * 32 + ns * 8 + 2 * t;
                float p0 = __expf(sc[ns][0] + SLOPE * (float)(k0c     - qrLo));
                float p1 = __expf(sc[ns][1] + SLOPE * (float)(k0c + 1 - qrLo));
                float p2 = __expf(sc[ns][2] + SLOPE * (float)(k0c     - qrHi));
                float p3 = __expf(sc[ns][3] + SLOPE * (float)(k0c + 1 - qrHi));
                if (diag) {
                    if (k0c     > qrLo) p0 = 0.0f;
                    if (k0c + 1 > qrLo) p1 = 0.0f;
                    if (k0c     > qrHi) p2 = 0.0f;
                    if (k0c + 1 > qrHi) p3 = 0.0f;
                }
                rs_lo += p0 + p1;
                rs_hi += p2 + p3;
                float* Pr = sm + SPP + (mw * 16 + g) * PP + nw * 32 + ns * 8 + 2 * t;
                *(float2*)Pr            = make_float2(tf32f(p0), tf32f(p1));
                *(float2*)(Pr + 8 * PP) = make_float2(tf32f(p2), tf32f(p3));
            }
            __syncthreads();   // P visible

            // ---- O += P V ----
            #pragma unroll
            for (int pk = 0; pk < 8; pk++) {
                uint32_t pa[4];
                const float* Pb = sm + SPP + (mw * 16 + g) * PP + pk * 8 + t;
                pa[0] = __float_as_uint(Pb[0]);
                pa[1] = __float_as_uint(Pb[8 * PP]);
                pa[2] = __float_as_uint(Pb[4]);
                pa[3] = __float_as_uint(Pb[8 * PP + 4]);
                const float* Vb = sm + SV + (pk * 8 + t) * VP + nw * 32 + g;
                #pragma unroll
                for (int ns = 0; ns < 4; ns++) {
                    uint32_t vb0 = __float_as_uint(Vb[ns * 8]);
                    uint32_t vb1 = __float_as_uint(Vb[ns * 8 + 4 * VP]);
                    mma8(of[ns], pa, vb0, vb1);
                }
            }
            __syncthreads();   // PV done; K/V/P free for next tile
        }

        // ---- epilogue: partial row sums + unnormalized O to scratch ----
        rs_lo += __shfl_xor_sync(0xffffffffu, rs_lo, 1);
        rs_lo += __shfl_xor_sync(0xffffffffu, rs_lo, 2);
        rs_hi += __shfl_xor_sync(0xffffffffu, rs_hi, 1);
        rs_hi += __shfl_xor_sync(0xffffffffu, rs_hi, 2);
        if (t == 0) {
            sm[SLS + nw * 64 + mw * 16 + g]     = rs_lo;
            sm[SLS + nw * 64 + mw * 16 + g + 8] = rs_hi;
        }
        __syncthreads();
        if (nw == 0 && t == 0) {
            const int rowL = mw * 16 + g;
            lP[bT + q0 + rowL]     = sm[SLS + rowL]     + sm[SLS + 64 + rowL];
            lP[bT + q0 + rowL + 8] = sm[SLS + rowL + 8] + sm[SLS + 64 + rowL + 8];
        }
        #pragma unroll
        for (int ns = 0; ns < 4; ns++) {
            float* orow = oP + (bT + q0 + mw * 16 + g) * HD + nw * 32 + ns * 8 + 2 * t;
            *(float2*)orow            = make_float2(of[ns][0], of[ns][1]);
            *(float2*)(orow + 8 * HD) = make_float2(of[ns][2], of[ns][3]);
        }
    }
}

// -------------------------------------------------------------------------
// Combine split-K partials: out = (O0 + O1) / (l0 + l1)
// -------------------------------------------------------------------------
__global__ __launch_bounds__(256) void combine_kernel(float* __restrict__ out)
{
    const int idx = blockIdx.x * 256 + threadIdx.x;   // float4 index
    const int row = idx >> 4;                         // 16 float4 per row
    float4 a = ((const float4*)g_oP)[idx];
    float4 c = ((const float4*)(g_oP + (size_t)MTOT * HD))[idx];
    const float inv = 1.0f / (g_lP[row] + g_lP[MTOT + row]);
    float4 r;
    r.x = (a.x + c.x) * inv;
    r.y = (a.y + c.y) * inv;
    r.z = (a.z + c.z) * inv;
    r.w = (a.w + c.w) * inv;
    ((float4*)out)[idx] = r;
}

// -------------------------------------------------------------------------
extern "C" void kernel_launch(void* const* d_in, const int* in_sizes, int n_in,
                              void* d_out, int out_size)
{
    const float* x  = (const float*)d_in[0];
    const float* wq = (const float*)d_in[1];
    const float* wk = (const float*)d_in[2];
    const float* wv = (const float*)d_in[3];
    float* out = (float*)d_out;

    (void)in_sizes; (void)n_in; (void)out_size;

    cudaFuncSetAttribute(qkv_gemm,
                         cudaFuncAttributeMaxDynamicSharedMemorySize, QKV_SMEM);
    cudaFuncSetAttribute(attn_kernel,
                         cudaFuncAttributeMaxDynamicSharedMemorySize, ATTN_SMEM);

    dim3 ggrid(MTOT / 128, 1, 3);        // 128 x 1 x 3
    qkv_gemm<<<ggrid, 256, QKV_SMEM>>>(x, wq, wk, wv);

    dim3 agrid(NCHUNK / 2, BATCH, 2);    // 32 x 4 x 2 = 256 blocks
    attn_kernel<<<agrid, 256, ATTN_SMEM>>>();

    combine_kernel<<<MTOT * HD / 1024, 256>>>(out);   // 1024 blocks
}

// round 12
// speedup vs baseline: 15.6681x; 1.2169x over previous
#include <cuda_runtime.h>
#include <cuda_bf16.h>
#include <cstdint>

// Problem constants
#define BATCH 4
#define TSEQ  4096
#define CEMB  1024
#define HD    64
#define MTOT  (BATCH * TSEQ)          // 16384 tokens

__device__ float g_q [MTOT * HD];     // [token][d] row-major (fp32)
__device__ float g_kF[MTOT * HD];     // B-fragment-major per 64-key tile (tf32 bits)
__device__ float g_v [MTOT * HD];     // [token][d] row-major (tf32-rounded)
__device__ float g_oP[2 * MTOT * HD]; // split-K partial O (unnormalized)
__device__ float g_lP[2 * MTOT];      // split-K partial row sums
__device__ __nv_bfloat16 g_wh[3 * HD * CEMB];  // [z*64+h][c] hi
__device__ __nv_bfloat16 g_wl[3 * HD * CEMB];  // [z*64+h][c] lo

// ---- tf32 / mma helpers --------------------------------------------------
__device__ __forceinline__ uint32_t f2tf(float f) {
    uint32_t u;
    asm("cvt.rna.tf32.f32 %0, %1;" : "=r"(u) : "f"(f));
    return u;
}
__device__ __forceinline__ float tf32f(float f) { return __uint_as_float(f2tf(f)); }

__device__ __forceinline__ void mma8(float c[4], const uint32_t a[4],
                                     uint32_t b0, uint32_t b1) {
    asm volatile(
        "mma.sync.aligned.m16n8k8.row.col.f32.tf32.tf32.f32 "
        "{%0,%1,%2,%3}, {%4,%5,%6,%7}, {%8,%9}, {%0,%1,%2,%3};"
        : "+f"(c[0]), "+f"(c[1]), "+f"(c[2]), "+f"(c[3])
        : "r"(a[0]), "r"(a[1]), "r"(a[2]), "r"(a[3]), "r"(b0), "r"(b1));
}

__device__ __forceinline__ void mma16(float c[4], const uint32_t a[4],
                                      const uint32_t b[2]) {
    asm volatile(
        "mma.sync.aligned.m16n8k16.row.col.f32.bf16.bf16.f32 "
        "{%0,%1,%2,%3}, {%4,%5,%6,%7}, {%8,%9}, {%0,%1,%2,%3};"
        : "+f"(c[0]), "+f"(c[1]), "+f"(c[2]), "+f"(c[3])
        : "r"(a[0]), "r"(a[1]), "r"(a[2]), "r"(a[3]), "r"(b[0]), "r"(b[1]));
}

#define CPA16(dst_s32, src) \
    asm volatile("cp.async.ca.shared.global [%0], [%1], 16;" :: "r"(dst_s32), "l"(src))
#define CPA_COMMIT() asm volatile("cp.async.commit_group;")
#define CPA_WAIT0()  asm volatile("cp.async.wait_group 0;" ::: "memory")

__device__ __forceinline__ uint32_t packbf(__nv_bfloat16 a, __nv_bfloat16 b) {
    __nv_bfloat162 v(a, b);
    return *reinterpret_cast<uint32_t*>(&v);
}
__device__ __forceinline__ void split2(float f0, float f1,
                                       uint32_t& h, uint32_t& l) {
    __nv_bfloat16 h0 = __float2bfloat16(f0);
    __nv_bfloat16 h1 = __float2bfloat16(f1);
    __nv_bfloat16 l0 = __float2bfloat16(f0 - __bfloat162float(h0));
    __nv_bfloat16 l1 = __float2bfloat16(f1 - __bfloat162float(h1));
    h = packbf(h0, h1);
    l = packbf(l0, l1);
}

// -------------------------------------------------------------------------
// Weight split prep: w (fp32 [h][c], 3 tensors) -> g_wh/g_wl bf16 [z*64+h][c]
// -------------------------------------------------------------------------
__global__ __launch_bounds__(256) void wprep_kernel(
    const float* __restrict__ wq,
    const float* __restrict__ wk,
    const float* __restrict__ wv)
{
    const int idx  = blockIdx.x * 256 + threadIdx.x;   // 0..49151
    const int base = idx * 4;
    const int row  = base >> 10;        // 0..191
    const int c    = base & 1023;
    const int z    = row >> 6;
    const int h    = row & 63;
    const float* w = (z == 0) ? wq : (z == 1) ? wk : wv;
    float4 v = *(const float4*)&w[(size_t)h * CEMB + c];
    uint32_t h01, l01, h23, l23;
    split2(v.x, v.y, h01, l01);
    split2(v.z, v.w, h23, l23);
    uint32_t* ph = (uint32_t*)&g_wh[base];
    uint32_t* pl = (uint32_t*)&g_wl[base];
    ph[0] = h01; ph[1] = h23;
    pl[0] = l01; pl[1] = l23;
}

// -------------------------------------------------------------------------
// Fused QKV projection on tensor cores: one block computes a 64(M) x 192(N)
// tile (N = [q|k|v] x 64) over K=1024. x staged+split ONCE per k-tile;
// weights cp.async'd pre-split. 8 warps as 2(m) x 4(n), warp tile 32x48.
// -------------------------------------------------------------------------
#define FKST 72   // smem k-stride (bf16 elems)
#define FXH 0
#define FXL (64 * FKST)            // 4608
#define FWH (2 * 64 * FKST)        // 9216
#define FWL (FWH + 192 * FKST)     // 23040
#define FUSED_SMEM_HALFS (FWL + 192 * FKST)
#define FUSED_SMEM ((int)(FUSED_SMEM_HALFS * sizeof(__nv_bfloat16)))  // 73,728 B

__global__ __launch_bounds__(256, 2) void qkv_fused(const float* __restrict__ x)
{
    extern __shared__ __nv_bfloat16 smh[];

    const int m0   = blockIdx.x * 64;
    const int tid  = threadIdx.x;
    const int lane = tid & 31;
    const int wid  = tid >> 5;
    const int mw   = wid >> 2;    // 0..1
    const int nw   = wid & 3;     // 0..3
    const int g    = lane >> 2;
    const int t    = lane & 3;

    float c[2][6][4] = {};

    for (int k0 = 0; k0 < CEMB; k0 += 64) {
        __syncthreads();   // previous compute done with smem

        // ---- cp.async weights hi/lo: 192 rows x 64 cols ----
        #pragma unroll
        for (int it = 0; it < 6; it++) {
            int ch  = tid + it * 256;        // 0..1535
            int r   = ch >> 3;               // 0..191
            int c8  = (ch & 7) * 8;          // 0..56
            uint32_t dh = (uint32_t)__cvta_generic_to_shared(
                &smh[FWH + r * FKST + c8]);
            uint32_t dl = (uint32_t)__cvta_generic_to_shared(
                &smh[FWL + r * FKST + c8]);
            CPA16(dh, &g_wh[(size_t)r * CEMB + k0 + c8]);
            CPA16(dl, &g_wl[(size_t)r * CEMB + k0 + c8]);
        }
        CPA_COMMIT();

        // ---- stage x tile 64x64 (fp32 -> hi/lo bf16), overlaps cp.async ----
        #pragma unroll
        for (int it = 0; it < 4; it++) {
            int f  = tid + it * 256;
            int r  = f >> 4;
            int c4 = (f & 15) * 4;
            float4 v = *(const float4*)&x[(size_t)(m0 + r) * CEMB + k0 + c4];
            uint32_t h01, l01, h23, l23;
            split2(v.x, v.y, h01, l01);
            split2(v.z, v.w, h23, l23);
            uint32_t* ph = (uint32_t*)&smh[FXH + r * FKST + c4];
            uint32_t* pl = (uint32_t*)&smh[FXL + r * FKST + c4];
            ph[0] = h01; ph[1] = h23;
            pl[0] = l01; pl[1] = l23;
        }
        CPA_WAIT0();
        __syncthreads();

        // ---- compute: 4 k16-steps ----
        #pragma unroll
        for (int s = 0; s < 4; s++) {
            const int kk = s * 16;
            uint32_t ah[2][4], al[2][4];
            #pragma unroll
            for (int mf = 0; mf < 2; mf++) {
                const int mr = mw * 32 + mf * 16 + g;
                const __nv_bfloat16* ph = &smh[FXH + mr * FKST + kk + 2 * t];
                const __nv_bfloat16* pl = &smh[FXL + mr * FKST + kk + 2 * t];
                ah[mf][0] = *(const uint32_t*)ph;
                ah[mf][1] = *(const uint32_t*)(ph + 8 * FKST);
                ah[mf][2] = *(const uint32_t*)(ph + 8);
                ah[mf][3] = *(const uint32_t*)(ph + 8 * FKST + 8);
                al[mf][0] = *(const uint32_t*)pl;
                al[mf][1] = *(const uint32_t*)(pl + 8 * FKST);
                al[mf][2] = *(const uint32_t*)(pl + 8);
                al[mf][3] = *(const uint32_t*)(pl + 8 * FKST + 8);
            }
            #pragma unroll
            for (int nf = 0; nf < 6; nf++) {
                const int nr = nw * 48 + nf * 8 + g;
                const __nv_bfloat16* ph = &smh[FWH + nr * FKST + kk + 2 * t];
                const __nv_bfloat16* pl = &smh[FWL + nr * FKST + kk + 2 * t];
                uint32_t bh[2], bl[2];
                bh[0] = *(const uint32_t*)ph;
                bh[1] = *(const uint32_t*)(ph + 8);
                bl[0] = *(const uint32_t*)pl;
                bl[1] = *(const uint32_t*)(pl + 8);
                mma16(c[0][nf], ah[0], bh);   // hi*hi
                mma16(c[1][nf], ah[1], bh);
                mma16(c[0][nf], al[0], bh);   // lo*hi
                mma16(c[1][nf], al[1], bh);
                mma16(c[0][nf], ah[0], bl);   // hi*lo
                mma16(c[1][nf], ah[1], bl);
            }
        }
    }

    // ---- epilogue: dispatch per fragment column group ----
    const int tile = m0 >> 6;   // for g_kF
    #pragma unroll
    for (int mf = 0; mf < 2; mf++) {
        const int r0 = m0 + mw * 32 + mf * 16 + g;
        #pragma unroll
        for (int nf = 0; nf < 6; nf++) {
            const int ncol = nw * 48 + nf * 8;   // 0..184, multiple of 8
            const int z    = ncol >> 6;          // 0=q, 1=k, 2=v
            const int d0   = (ncol & 63) + 2 * t;
            if (z == 0) {
                *(float2*)&g_q[(size_t)r0 * HD + d0] =
                    make_float2(c[mf][nf][0], c[mf][nf][1]);
                *(float2*)&g_q[(size_t)(r0 + 8) * HD + d0] =
                    make_float2(c[mf][nf][2], c[mf][nf][3]);
            } else if (z == 2) {
                *(float2*)&g_v[(size_t)r0 * HD + d0] =
                    make_float2(tf32f(c[mf][nf][0]), tf32f(c[mf][nf][1]));
                *(float2*)&g_v[(size_t)(r0 + 8) * HD + d0] =
                    make_float2(tf32f(c[mf][nf][2]), tf32f(c[mf][nf][3]));
            } else {
                // K -> B-fragment-major tf32 layout for the attention kernel
                const int d8 = (ncol & 63) >> 3;
                #pragma unroll
                for (int hi = 0; hi < 2; hi++) {
                    const int key = r0 + hi * 8;
                    const int n8  = (key >> 3) & 7;
                    float* tb = g_kF + (size_t)tile * 4096
                              + (d8 * 8 + n8) * 64 + g * 8;
                    #pragma unroll
                    for (int jj = 0; jj < 2; jj++) {
                        const int dm = 2 * t + jj;
                        tb[(dm & 3) * 2 + (dm >> 2)] =
                            tf32f(c[mf][nf][hi * 2 + jj]);
                    }
                }
            }
        }
    }
}

// -------------------------------------------------------------------------
// Flash attention on tensor cores, split-K across blockIdx.z (tile parity).
// (unchanged from R6)
// -------------------------------------------------------------------------
#define NCHUNK (TSEQ / 64)
#define VP 72
#define PP 68
#define SK  0
#define SV  4096
#define SPP (SV + 64 * VP)                 // 8704
#define SLS (SPP + 64 * PP)                // 13056
#define ATTN_SMEM ((SLS + 128) * 4)        // 52,736 B

__global__ __launch_bounds__(256, 2) void attn_kernel()
{
    constexpr float SCALE = 0.03125f;
    constexpr float SLOPE = 0.70710678118654752f;

    extern __shared__ float sm[];
    const int b    = blockIdx.y;
    const int sz   = blockIdx.z;
    const size_t bT = (size_t)b * TSEQ;
    const int tid  = threadIdx.x;
    const int lane = tid & 31;
    const int wid  = tid >> 5;
    const int mw   = wid >> 1;
    const int nw   = wid & 1;
    const int g    = lane >> 2;
    const int t    = lane & 3;

    float* oP = g_oP + (size_t)sz * MTOT * HD;
    float* lP = g_lP + (size_t)sz * MTOT;

    #pragma unroll 1
    for (int half = 0; half < 2; half++) {
        const int chunk = half ? (NCHUNK - 1 - (int)blockIdx.x) : (int)blockIdx.x;
        const int q0 = chunk * 64;
        const int nT = chunk + 1;

        __syncthreads();

        uint32_t qa[8][4];
        {
            const float* qp  = g_q + (bT + q0 + mw * 16 + g) * HD;
            const float* qp8 = qp + 8 * HD;
            #pragma unroll
            for (int tk = 0; tk < 8; tk++) {
                qa[tk][0] = f2tf(qp [tk * 8 + t]     * SCALE);
                qa[tk][1] = f2tf(qp8[tk * 8 + t]     * SCALE);
                qa[tk][2] = f2tf(qp [tk * 8 + t + 4] * SCALE);
                qa[tk][3] = f2tf(qp8[tk * 8 + t + 4] * SCALE);
            }
        }

        float of[4][4] = {};
        float rs_lo = 0.0f, rs_hi = 0.0f;

        #pragma unroll 1
        for (int tt = sz; tt < nT; tt += 2) {
            const int j0 = tt * 64;

            {
                const float* ks = g_kF + (bT + j0) * 64;
                #pragma unroll
                for (int it = 0; it < 4; it++) {
                    int f4 = it * 256 + tid;
                    uint32_t d = (uint32_t)__cvta_generic_to_shared(sm + SK + f4 * 4);
                    CPA16(d, ks + f4 * 4);
                }
                #pragma unroll
                for (int it = 0; it < 4; it++) {
                    int f = it * 256 + tid;
                    int r = f >> 4, c4 = (f & 15) * 4;
                    uint32_t d = (uint32_t)__cvta_generic_to_shared(sm + SV + r * VP + c4);
                    CPA16(d, g_v + (bT + j0 + r) * HD + c4);
                }
                CPA_COMMIT();
            }
            CPA_WAIT0();
            __syncthreads();

            float sc[4][4] = {};
            #pragma unroll
            for (int tk = 0; tk < 8; tk++) {
                #pragma unroll
                for (int ns = 0; ns < 4; ns++) {
                    float2 kb = *(const float2*)
                        &sm[SK + ((tk * 8 + nw * 4 + ns) * 32 + lane) * 2];
                    mma8(sc[ns], qa[tk],
                         __float_as_uint(kb.x), __float_as_uint(kb.y));
                }
            }

            const bool diag = (tt == nT - 1);
            const int qrLo = q0 + mw * 16 + g;
            const int qrHi = qrLo + 8;
            #pragma unroll
            for (int ns = 0; ns < 4; ns++) {
                const int k0c = j0 + nw * 32 + ns * 8 + 2 * t;
                float p0 = __expf(sc[ns][0] + SLOPE * (float)(k0c     - qrLo));
                float p1 = __expf(sc[ns][1] + SLOPE * (float)(k0c + 1 - qrLo));
                float p2 = __expf(sc[ns][2] + SLOPE * (float)(k0c     - qrHi));
                float p3 = __expf(sc[ns][3] + SLOPE * (float)(k0c + 1 - qrHi));
                if (diag) {
                    if (k0c     > qrLo) p0 = 0.0f;
                    if (k0c + 1 > qrLo) p1 = 0.0f;
                    if (k0c     > qrHi) p2 = 0.0f;
                    if (k0c + 1 > qrHi) p3 = 0.0f;
                }
                rs_lo += p0 + p1;
                rs_hi += p2 + p3;
                float* Pr = sm + SPP + (mw * 16 + g) * PP + nw * 32 + ns * 8 + 2 * t;
                *(float2*)Pr            = make_float2(tf32f(p0), tf32f(p1));
                *(float2*)(Pr + 8 * PP) = make_float2(tf32f(p2), tf32f(p3));
            }
            __syncthreads();

            #pragma unroll
            for (int pk = 0; pk < 8; pk++) {
                uint32_t pa[4];
                const float* Pb = sm + SPP + (mw * 16 + g) * PP + pk * 8 + t;
                pa[0] = __float_as_uint(Pb[0]);
                pa[1] = __float_as_uint(Pb[8 * PP]);
                pa[2] = __float_as_uint(Pb[4]);
                pa[3] = __float_as_uint(Pb[8 * PP + 4]);
                const float* Vb = sm + SV + (pk * 8 + t) * VP + nw * 32 + g;
                #pragma unroll
                for (int ns = 0; ns < 4; ns++) {
                    uint32_t vb0 = __float_as_uint(Vb[ns * 8]);
                    uint32_t vb1 = __float_as_uint(Vb[ns * 8 + 4 * VP]);
                    mma8(of[ns], pa, vb0, vb1);
                }
            }
            __syncthreads();
        }

        rs_lo += __shfl_xor_sync(0xffffffffu, rs_lo, 1);
        rs_lo += __shfl_xor_sync(0xffffffffu, rs_lo, 2);
        rs_hi += __shfl_xor_sync(0xffffffffu, rs_hi, 1);
        rs_hi += __shfl_xor_sync(0xffffffffu, rs_hi, 2);
        if (t == 0) {
            sm[SLS + nw * 64 + mw * 16 + g]     = rs_lo;
            sm[SLS + nw * 64 + mw * 16 + g + 8] = rs_hi;
        }
        __syncthreads();
        if (nw == 0 && t == 0) {
            const int rowL = mw * 16 + g;
            lP[bT + q0 + rowL]     = sm[SLS + rowL]     + sm[SLS + 64 + rowL];
            lP[bT + q0 + rowL + 8] = sm[SLS + rowL + 8] + sm[SLS + 64 + rowL + 8];
        }
        #pragma unroll
        for (int ns = 0; ns < 4; ns++) {
            float* orow = oP + (bT + q0 + mw * 16 + g) * HD + nw * 32 + ns * 8 + 2 * t;
            *(float2*)orow            = make_float2(of[ns][0], of[ns][1]);
            *(float2*)(orow + 8 * HD) = make_float2(of[ns][2], of[ns][3]);
        }
    }
}

// -------------------------------------------------------------------------
// Combine split-K partials: out = (O0 + O1) / (l0 + l1)
// -------------------------------------------------------------------------
__global__ __launch_bounds__(256) void combine_kernel(float* __restrict__ out)
{
    const int idx = blockIdx.x * 256 + threadIdx.x;
    const int row = idx >> 4;
    float4 a = ((const float4*)g_oP)[idx];
    float4 c = ((const float4*)(g_oP + (size_t)MTOT * HD))[idx];
    const float inv = 1.0f / (g_lP[row] + g_lP[MTOT + row]);
    float4 r;
    r.x = (a.x + c.x) * inv;
    r.y = (a.y + c.y) * inv;
    r.z = (a.z + c.z) * inv;
    r.w = (a.w + c.w) * inv;
    ((float4*)out)[idx] = r;
}

// -------------------------------------------------------------------------
extern "C" void kernel_launch(void* const* d_in, const int* in_sizes, int n_in,
                              void* d_out, int out_size)
{
    const float* x  = (const float*)d_in[0];
    const float* wq = (const float*)d_in[1];
    const float* wk = (const float*)d_in[2];
    const float* wv = (const float*)d_in[3];
    float* out = (float*)d_out;

    (void)in_sizes; (void)n_in; (void)out_size;

    cudaFuncSetAttribute(qkv_fused,
                         cudaFuncAttributeMaxDynamicSharedMemorySize, FUSED_SMEM);
    cudaFuncSetAttribute(attn_kernel,
                         cudaFuncAttributeMaxDynamicSharedMemorySize, ATTN_SMEM);

    wprep_kernel<<<192, 256>>>(wq, wk, wv);               // 196K elems

    qkv_fused<<<MTOT / 64, 256, FUSED_SMEM>>>(x);         // 256 blocks

    dim3 agrid(NCHUNK / 2, BATCH, 2);                     // 32 x 4 x 2
    attn_kernel<<<agrid, 256, ATTN_SMEM>>>();

    combine_kernel<<<MTOT * HD / 1024, 256>>>(out);       // 1024 blocks
}

// round 13
// speedup vs baseline: 16.0528x; 1.0246x over previous
#include <cuda_runtime.h>
#include <cuda_bf16.h>
#include <cstdint>

// Problem constants
#define BATCH 4
#define TSEQ  4096
#define CEMB  1024
#define HD    64
#define MTOT  (BATCH * TSEQ)          // 16384 tokens

__device__ float g_q [MTOT * HD];     // [token][d] row-major (fp32)
__device__ float g_kF[MTOT * HD];     // B-fragment-major per 64-key tile (tf32 bits)
__device__ float g_v [MTOT * HD];     // [token][d] row-major (tf32-rounded)
__device__ float g_oP[2 * MTOT * HD]; // split-K partial O (unnormalized)
__device__ float g_lP[2 * MTOT];      // split-K partial row sums
__device__ __nv_bfloat16 g_wh[3 * HD * CEMB];  // [z*64+h][c] hi
__device__ __nv_bfloat16 g_wl[3 * HD * CEMB];  // [z*64+h][c] lo

// ---- tf32 / mma helpers --------------------------------------------------
__device__ __forceinline__ uint32_t f2tf(float f) {
    uint32_t u;
    asm("cvt.rna.tf32.f32 %0, %1;" : "=r"(u) : "f"(f));
    return u;
}
__device__ __forceinline__ float tf32f(float f) { return __uint_as_float(f2tf(f)); }

__device__ __forceinline__ void mma8(float c[4], const uint32_t a[4],
                                     uint32_t b0, uint32_t b1) {
    asm volatile(
        "mma.sync.aligned.m16n8k8.row.col.f32.tf32.tf32.f32 "
        "{%0,%1,%2,%3}, {%4,%5,%6,%7}, {%8,%9}, {%0,%1,%2,%3};"
        : "+f"(c[0]), "+f"(c[1]), "+f"(c[2]), "+f"(c[3])
        : "r"(a[0]), "r"(a[1]), "r"(a[2]), "r"(a[3]), "r"(b0), "r"(b1));
}

__device__ __forceinline__ void mma16(float c[4], const uint32_t a[4],
                                      const uint32_t b[2]) {
    asm volatile(
        "mma.sync.aligned.m16n8k16.row.col.f32.bf16.bf16.f32 "
        "{%0,%1,%2,%3}, {%4,%5,%6,%7}, {%8,%9}, {%0,%1,%2,%3};"
        : "+f"(c[0]), "+f"(c[1]), "+f"(c[2]), "+f"(c[3])
        : "r"(a[0]), "r"(a[1]), "r"(a[2]), "r"(a[3]), "r"(b[0]), "r"(b[1]));
}

#define CPA16(dst_s32, src) \
    asm volatile("cp.async.ca.shared.global [%0], [%1], 16;" :: "r"(dst_s32), "l"(src))
#define CPA_COMMIT() asm volatile("cp.async.commit_group;")
#define CPA_WAIT0()  asm volatile("cp.async.wait_group 0;" ::: "memory")

__device__ __forceinline__ uint32_t packbf(__nv_bfloat16 a, __nv_bfloat16 b) {
    __nv_bfloat162 v(a, b);
    return *reinterpret_cast<uint32_t*>(&v);
}
__device__ __forceinline__ void split2(float f0, float f1,
                                       uint32_t& h, uint32_t& l) {
    __nv_bfloat16 h0 = __float2bfloat16(f0);
    __nv_bfloat16 h1 = __float2bfloat16(f1);
    __nv_bfloat16 l0 = __float2bfloat16(f0 - __bfloat162float(h0));
    __nv_bfloat16 l1 = __float2bfloat16(f1 - __bfloat162float(h1));
    h = packbf(h0, h1);
    l = packbf(l0, l1);
}

// -------------------------------------------------------------------------
// Weight split prep: w (fp32 [h][c], 3 tensors) -> g_wh/g_wl bf16 [z*64+h][c]
// -------------------------------------------------------------------------
__global__ __launch_bounds__(256) void wprep_kernel(
    const float* __restrict__ wq,
    const float* __restrict__ wk,
    const float* __restrict__ wv)
{
    const int idx  = blockIdx.x * 256 + threadIdx.x;   // 0..49151
    const int base = idx * 4;
    const int row  = base >> 10;        // 0..191
    const int c    = base & 1023;
    const int z    = row >> 6;
    const int h    = row & 63;
    const float* w = (z == 0) ? wq : (z == 1) ? wk : wv;
    float4 v = *(const float4*)&w[(size_t)h * CEMB + c];
    uint32_t h01, l01, h23, l23;
    split2(v.x, v.y, h01, l01);
    split2(v.z, v.w, h23, l23);
    uint32_t* ph = (uint32_t*)&g_wh[base];
    uint32_t* pl = (uint32_t*)&g_wl[base];
    ph[0] = h01; ph[1] = h23;
    pl[0] = l01; pl[1] = l23;
}

// -------------------------------------------------------------------------
// Fused QKV projection on tensor cores (unchanged from R11).
// -------------------------------------------------------------------------
#define FKST 72   // smem k-stride (bf16 elems)
#define FXH 0
#define FXL (64 * FKST)            // 4608
#define FWH (2 * 64 * FKST)        // 9216
#define FWL (FWH + 192 * FKST)     // 23040
#define FUSED_SMEM_HALFS (FWL + 192 * FKST)
#define FUSED_SMEM ((int)(FUSED_SMEM_HALFS * sizeof(__nv_bfloat16)))  // 73,728 B

__global__ __launch_bounds__(256, 2) void qkv_fused(const float* __restrict__ x)
{
    extern __shared__ __nv_bfloat16 smh[];

    const int m0   = blockIdx.x * 64;
    const int tid  = threadIdx.x;
    const int lane = tid & 31;
    const int wid  = tid >> 5;
    const int mw   = wid >> 2;    // 0..1
    const int nw   = wid & 3;     // 0..3
    const int g    = lane >> 2;
    const int t    = lane & 3;

    float c[2][6][4] = {};

    for (int k0 = 0; k0 < CEMB; k0 += 64) {
        __syncthreads();

        #pragma unroll
        for (int it = 0; it < 6; it++) {
            int ch  = tid + it * 256;
            int r   = ch >> 3;
            int c8  = (ch & 7) * 8;
            uint32_t dh = (uint32_t)__cvta_generic_to_shared(
                &smh[FWH + r * FKST + c8]);
            uint32_t dl = (uint32_t)__cvta_generic_to_shared(
                &smh[FWL + r * FKST + c8]);
            CPA16(dh, &g_wh[(size_t)r * CEMB + k0 + c8]);
            CPA16(dl, &g_wl[(size_t)r * CEMB + k0 + c8]);
        }
        CPA_COMMIT();

        #pragma unroll
        for (int it = 0; it < 4; it++) {
            int f  = tid + it * 256;
            int r  = f >> 4;
            int c4 = (f & 15) * 4;
            float4 v = *(const float4*)&x[(size_t)(m0 + r) * CEMB + k0 + c4];
            uint32_t h01, l01, h23, l23;
            split2(v.x, v.y, h01, l01);
            split2(v.z, v.w, h23, l23);
            uint32_t* ph = (uint32_t*)&smh[FXH + r * FKST + c4];
            uint32_t* pl = (uint32_t*)&smh[FXL + r * FKST + c4];
            ph[0] = h01; ph[1] = h23;
            pl[0] = l01; pl[1] = l23;
        }
        CPA_WAIT0();
        __syncthreads();

        #pragma unroll
        for (int s = 0; s < 4; s++) {
            const int kk = s * 16;
            uint32_t ah[2][4], al[2][4];
            #pragma unroll
            for (int mf = 0; mf < 2; mf++) {
                const int mr = mw * 32 + mf * 16 + g;
                const __nv_bfloat16* ph = &smh[FXH + mr * FKST + kk + 2 * t];
                const __nv_bfloat16* pl = &smh[FXL + mr * FKST + kk + 2 * t];
                ah[mf][0] = *(const uint32_t*)ph;
                ah[mf][1] = *(const uint32_t*)(ph + 8 * FKST);
                ah[mf][2] = *(const uint32_t*)(ph + 8);
                ah[mf][3] = *(const uint32_t*)(ph + 8 * FKST + 8);
                al[mf][0] = *(const uint32_t*)pl;
                al[mf][1] = *(const uint32_t*)(pl + 8 * FKST);
                al[mf][2] = *(const uint32_t*)(pl + 8);
                al[mf][3] = *(const uint32_t*)(pl + 8 * FKST + 8);
            }
            #pragma unroll
            for (int nf = 0; nf < 6; nf++) {
                const int nr = nw * 48 + nf * 8 + g;
                const __nv_bfloat16* ph = &smh[FWH + nr * FKST + kk + 2 * t];
                const __nv_bfloat16* pl = &smh[FWL + nr * FKST + kk + 2 * t];
                uint32_t bh[2], bl[2];
                bh[0] = *(const uint32_t*)ph;
                bh[1] = *(const uint32_t*)(ph + 8);
                bl[0] = *(const uint32_t*)pl;
                bl[1] = *(const uint32_t*)(pl + 8);
                mma16(c[0][nf], ah[0], bh);
                mma16(c[1][nf], ah[1], bh);
                mma16(c[0][nf], al[0], bh);
                mma16(c[1][nf], al[1], bh);
                mma16(c[0][nf], ah[0], bl);
                mma16(c[1][nf], ah[1], bl);
            }
        }
    }

    const int tile = m0 >> 6;
    #pragma unroll
    for (int mf = 0; mf < 2; mf++) {
        const int r0 = m0 + mw * 32 + mf * 16 + g;
        #pragma unroll
        for (int nf = 0; nf < 6; nf++) {
            const int ncol = nw * 48 + nf * 8;
            const int z    = ncol >> 6;
            const int d0   = (ncol & 63) + 2 * t;
            if (z == 0) {
                *(float2*)&g_q[(size_t)r0 * HD + d0] =
                    make_float2(c[mf][nf][0], c[mf][nf][1]);
                *(float2*)&g_q[(size_t)(r0 + 8) * HD + d0] =
                    make_float2(c[mf][nf][2], c[mf][nf][3]);
            } else if (z == 2) {
                *(float2*)&g_v[(size_t)r0 * HD + d0] =
                    make_float2(tf32f(c[mf][nf][0]), tf32f(c[mf][nf][1]));
                *(float2*)&g_v[(size_t)(r0 + 8) * HD + d0] =
                    make_float2(tf32f(c[mf][nf][2]), tf32f(c[mf][nf][3]));
            } else {
                const int d8 = (ncol & 63) >> 3;
                #pragma unroll
                for (int hi = 0; hi < 2; hi++) {
                    const int key = r0 + hi * 8;
                    const int n8  = (key >> 3) & 7;
                    float* tb = g_kF + (size_t)tile * 4096
                              + (d8 * 8 + n8) * 64 + g * 8;
                    #pragma unroll
                    for (int jj = 0; jj < 2; jj++) {
                        const int dm = 2 * t + jj;
                        tb[(dm & 3) * 2 + (dm >> 2)] =
                            tf32f(c[mf][nf][hi * 2 + jj]);
                    }
                }
            }
        }
    }
}

// -------------------------------------------------------------------------
// Flash attention on tensor cores, BQ=128 (8 warps as 4m x 2n, warp tile
// 32x32). Halves staging/K-frag traffic per query row vs BQ=64. Split-K
// across blockIdx.z tile parity; unnormalized partials to scratch.
// -------------------------------------------------------------------------
#define NCHUNK2 (TSEQ / 128)   // 32
#define VP 72
#define PP 68
#define SK  0
#define SV  4096
#define SPP (SV + 64 * VP)                 // 8704
#define SLS (SPP + 128 * PP)               // 17408
#define ATTN_SMEM ((SLS + 256) * 4)        // 70,656 B

__global__ __launch_bounds__(256) void attn_kernel()
{
    constexpr float SCALE = 0.03125f;
    constexpr float SLOPE = 0.70710678118654752f;

    extern __shared__ float sm[];
    const int b    = blockIdx.y;
    const int sz   = blockIdx.z;           // tile parity 0/1
    const size_t bT = (size_t)b * TSEQ;
    const int tid  = threadIdx.x;
    const int lane = tid & 31;
    const int wid  = tid >> 5;
    const int mw   = wid >> 1;   // 0..3 : 32-row slice
    const int nw   = wid & 1;    // 0..1 : 32-key slice
    const int g    = lane >> 2;
    const int t    = lane & 3;

    float* oP = g_oP + (size_t)sz * MTOT * HD;
    float* lP = g_lP + (size_t)sz * MTOT;

    #pragma unroll 1
    for (int half = 0; half < 2; half++) {
        const int chunk = half ? (NCHUNK2 - 1 - (int)blockIdx.x) : (int)blockIdx.x;
        const int q0 = chunk * 128;
        const int nT = 2 * chunk + 2;

        __syncthreads();   // previous chunk fully done with smem

        // ---- Q A-fragments for 2 m-frags, register resident per chunk ----
        uint32_t qa[2][8][4];
        #pragma unroll
        for (int mf = 0; mf < 2; mf++) {
            const float* qp  = g_q + (bT + q0 + mw * 32 + mf * 16 + g) * HD;
            const float* qp8 = qp + 8 * HD;
            #pragma unroll
            for (int tk = 0; tk < 8; tk++) {
                qa[mf][tk][0] = f2tf(qp [tk * 8 + t]     * SCALE);
                qa[mf][tk][1] = f2tf(qp8[tk * 8 + t]     * SCALE);
                qa[mf][tk][2] = f2tf(qp [tk * 8 + t + 4] * SCALE);
                qa[mf][tk][3] = f2tf(qp8[tk * 8 + t + 4] * SCALE);
            }
        }

        float of[2][4][4] = {};
        float rs[2][2] = {};

        #pragma unroll 1
        for (int tt = sz; tt < nT; tt += 2) {
            const int j0 = tt * 64;

            // ---- stage K/V tile ----
            {
                const float* ks = g_kF + (bT + j0) * 64;
                #pragma unroll
                for (int it = 0; it < 4; it++) {
                    int f4 = it * 256 + tid;
                    uint32_t d = (uint32_t)__cvta_generic_to_shared(sm + SK + f4 * 4);
                    CPA16(d, ks + f4 * 4);
                }
                #pragma unroll
                for (int it = 0; it < 4; it++) {
                    int f = it * 256 + tid;
                    int r = f >> 4, c4 = (f & 15) * 4;
                    uint32_t d = (uint32_t)__cvta_generic_to_shared(sm + SV + r * VP + c4);
                    CPA16(d, g_v + (bT + j0 + r) * HD + c4);
                }
                CPA_COMMIT();
            }
            CPA_WAIT0();
            __syncthreads();

            // ---- S = Q K^T ----
            float sc[2][4][4] = {};
            #pragma unroll
            for (int tk = 0; tk < 8; tk++) {
                #pragma unroll
                for (int ns = 0; ns < 4; ns++) {
                    float2 kb = *(const float2*)
                        &sm[SK + ((tk * 8 + nw * 4 + ns) * 32 + lane) * 2];
                    const uint32_t b0 = __float_as_uint(kb.x);
                    const uint32_t b1 = __float_as_uint(kb.y);
                    mma8(sc[0][ns], qa[0][tk], b0, b1);
                    mma8(sc[1][ns], qa[1][tk], b0, b1);
                }
            }

            // ---- ALiBi + causal + exp, stage P ----
            const bool diag = (j0 >= q0);
            #pragma unroll
            for (int mf = 0; mf < 2; mf++) {
                const int qrLo = q0 + mw * 32 + mf * 16 + g;
                const int qrHi = qrLo + 8;
                #pragma unroll
                for (int ns = 0; ns < 4; ns++) {
                    const int k0c = j0 + nw * 32 + ns * 8 + 2 * t;
                    float p0 = __expf(sc[mf][ns][0] + SLOPE * (float)(k0c     - qrLo));
                    float p1 = __expf(sc[mf][ns][1] + SLOPE * (float)(k0c + 1 - qrLo));
                    float p2 = __expf(sc[mf][ns][2] + SLOPE * (float)(k0c     - qrHi));
                    float p3 = __expf(sc[mf][ns][3] + SLOPE * (float)(k0c + 1 - qrHi));
                    if (diag) {
                        if (k0c     > qrLo) p0 = 0.0f;
                        if (k0c + 1 > qrLo) p1 = 0.0f;
                        if (k0c     > qrHi) p2 = 0.0f;
                        if (k0c + 1 > qrHi) p3 = 0.0f;
                    }
                    rs[mf][0] += p0 + p1;
                    rs[mf][1] += p2 + p3;
                    float* Pr = sm + SPP + (mw * 32 + mf * 16 + g) * PP
                              + nw * 32 + ns * 8 + 2 * t;
                    *(float2*)Pr            = make_float2(tf32f(p0), tf32f(p1));
                    *(float2*)(Pr + 8 * PP) = make_float2(tf32f(p2), tf32f(p3));
                }
            }
            __syncthreads();   // P visible

            // ---- O += P V ----
            #pragma unroll
            for (int pk = 0; pk < 8; pk++) {
                uint32_t pa[2][4];
                #pragma unroll
                for (int mf = 0; mf < 2; mf++) {
                    const float* Pb = sm + SPP + (mw * 32 + mf * 16 + g) * PP
                                    + pk * 8 + t;
                    pa[mf][0] = __float_as_uint(Pb[0]);
                    pa[mf][1] = __float_as_uint(Pb[8 * PP]);
                    pa[mf][2] = __float_as_uint(Pb[4]);
                    pa[mf][3] = __float_as_uint(Pb[8 * PP + 4]);
                }
                const float* Vb = sm + SV + (pk * 8 + t) * VP + nw * 32 + g;
                #pragma unroll
                for (int ns = 0; ns < 4; ns++) {
                    uint32_t vb0 = __float_as_uint(Vb[ns * 8]);
                    uint32_t vb1 = __float_as_uint(Vb[ns * 8 + 4 * VP]);
                    mma8(of[0][ns], pa[0], vb0, vb1);
                    mma8(of[1][ns], pa[1], vb0, vb1);
                }
            }
            __syncthreads();   // PV done; K/V/P free for next tile
        }

        // ---- epilogue: partial row sums + unnormalized O to scratch ----
        #pragma unroll
        for (int mf = 0; mf < 2; mf++)
            #pragma unroll
            for (int hv = 0; hv < 2; hv++) {
                float l = rs[mf][hv];
                l += __shfl_xor_sync(0xffffffffu, l, 1);
                l += __shfl_xor_sync(0xffffffffu, l, 2);
                if (t == 0)
                    sm[SLS + nw * 128 + mw * 32 + mf * 16 + hv * 8 + g] = l;
            }
        __syncthreads();
        if (nw == 0 && t == 0) {
            #pragma unroll
            for (int mf = 0; mf < 2; mf++)
                #pragma unroll
                for (int hv = 0; hv < 2; hv++) {
                    const int row = mw * 32 + mf * 16 + hv * 8 + g;
                    lP[bT + q0 + row] = sm[SLS + row] + sm[SLS + 128 + row];
                }
        }
        #pragma unroll
        for (int mf = 0; mf < 2; mf++) {
            const int row = mw * 32 + mf * 16 + g;
            #pragma unroll
            for (int ns = 0; ns < 4; ns++) {
                float* orow = oP + (bT + q0 + row) * HD + nw * 32 + ns * 8 + 2 * t;
                *(float2*)orow            = make_float2(of[mf][ns][0], of[mf][ns][1]);
                *(float2*)(orow + 8 * HD) = make_float2(of[mf][ns][2], of[mf][ns][3]);
            }
        }
    }
}

// -------------------------------------------------------------------------
// Combine split-K partials: out = (O0 + O1) / (l0 + l1)
// -------------------------------------------------------------------------
__global__ __launch_bounds__(256) void combine_kernel(float* __restrict__ out)
{
    const int idx = blockIdx.x * 256 + threadIdx.x;
    const int row = idx >> 4;
    float4 a = ((const float4*)g_oP)[idx];
    float4 c = ((const float4*)(g_oP + (size_t)MTOT * HD))[idx];
    const float inv = 1.0f / (g_lP[row] + g_lP[MTOT + row]);
    float4 r;
    r.x = (a.x + c.x) * inv;
    r.y = (a.y + c.y) * inv;
    r.z = (a.z + c.z) * inv;
    r.w = (a.w + c.w) * inv;
    ((float4*)out)[idx] = r;
}

// -------------------------------------------------------------------------
extern "C" void kernel_launch(void* const* d_in, const int* in_sizes, int n_in,
                              void* d_out, int out_size)
{
    const float* x  = (const float*)d_in[0];
    const float* wq = (const float*)d_in[1];
    const float* wk = (const float*)d_in[2];
    const float* wv = (const float*)d_in[3];
    float* out = (float*)d_out;

    (void)in_sizes; (void)n_in; (void)out_size;

    cudaFuncSetAttribute(qkv_fused,
                         cudaFuncAttributeMaxDynamicSharedMemorySize, FUSED_SMEM);
    cudaFuncSetAttribute(attn_kernel,
                         cudaFuncAttributeMaxDynamicSharedMemorySize, ATTN_SMEM);

    wprep_kernel<<<192, 256>>>(wq, wk, wv);               // 196K elems

    qkv_fused<<<MTOT / 64, 256, FUSED_SMEM>>>(x);         // 256 blocks

    dim3 agrid(NCHUNK2 / 2, BATCH, 2);                    // 16 x 4 x 2 = 128
    attn_kernel<<<agrid, 256, ATTN_SMEM>>>();

    combine_kernel<<<MTOT * HD / 1024, 256>>>(out);       // 1024 blocks
}